// round 9
// baseline (speedup 1.0000x reference)
#include <cuda_runtime.h>
#include <cuda_bf16.h>
#include <math.h>
#include <cstdint>

// ---------------------------------------------------------------------------
// Problem constants
// ---------------------------------------------------------------------------
#define BATCH 4
#define SEQ   1024
#define D     768
#define DH    769
#define HEADS 12
#define HDIM  64
#define BH    (BATCH*HEADS)      // 48
#define ROWS  (BATCH*SEQ)        // 4096
#define DM    3072
#define DMH   3073
#define KP1   800
#define KP2   3104

// ---------------------------------------------------------------------------
// Scratch
// ---------------------------------------------------------------------------
__device__ float g_QKVf[3*BH*SEQ*HDIM];   // Q | K | V per-head fp32
__device__ float g_qt [BH*SEQ];
__device__ float g_kt [BH*SEQ];
__device__ float g_Th [ROWS*HEADS];
__device__ float g_MO [ROWS*D];
__device__ float g_OUT[ROWS*D];
__device__ float g_G2 [ROWS*D];

// bf16 per-head planes for attention (Q,K single; V split)
__device__ __nv_bfloat16 g_Qsph[BH*SEQ*HDIM];
__device__ __nv_bfloat16 g_Ksph[BH*SEQ*HDIM];
__device__ __nv_bfloat16 g_Vsph[BH*SEQ*HDIM], g_Vspl[BH*SEQ*HDIM];

// split-bf16 activation planes
__device__ __nv_bfloat16 g_X1h [ROWS*KP1], g_X1l [ROWS*KP1];
__device__ __nv_bfloat16 g_AINh[ROWS*KP1], g_AINl[ROWS*KP1];
__device__ __nv_bfloat16 g_Hh  [ROWS*KP1], g_Hl  [ROWS*KP1];
__device__ __nv_bfloat16 g_H1h [ROWS*KP2], g_H1l [ROWS*KP2];

// split-bf16 weight planes
__device__ __nv_bfloat16 g_Wqkvh[3*D*KP1], g_Wqkvl[3*D*KP1];
__device__ __nv_bfloat16 g_Woh[D*KP1],  g_Wol[D*KP1];
__device__ __nv_bfloat16 g_W1h[DM*KP1], g_W1l[DM*KP1];
__device__ __nv_bfloat16 g_W2h[D*KP2],  g_W2l[D*KP2];

// ---------------------------------------------------------------------------
// Helpers
// ---------------------------------------------------------------------------
__device__ __forceinline__ float warpSum(float v){
  #pragma unroll
  for(int o=16;o>0;o>>=1) v += __shfl_xor_sync(0xffffffffu, v, o);
  return v;
}
__device__ __forceinline__ float blockSum(float v, float* sh){
  int lane = threadIdx.x & 31, w = threadIdx.x >> 5;
  v = warpSum(v);
  if(lane==0) sh[w] = v;
  __syncthreads();
  float r = (threadIdx.x < 8) ? sh[threadIdx.x] : 0.f;
  if(w==0) r = warpSum(r);
  if(threadIdx.x==0) sh[0] = r;
  __syncthreads();
  r = sh[0];
  __syncthreads();
  return r;
}
__device__ __forceinline__ void splitStore(__nv_bfloat16* ph, __nv_bfloat16* pl, float x){
  __nv_bfloat16 h = __float2bfloat16(x);
  *ph = h;
  *pl = __float2bfloat16(x - __bfloat162float(h));
}
__device__ __forceinline__ void packhi(float a, float b, unsigned &h){
  __nv_bfloat162 hp; hp.x = __float2bfloat16(a); hp.y = __float2bfloat16(b);
  h = *(unsigned*)&hp;
}
__device__ __forceinline__ void cpasync16(void* s, const void* g){
  unsigned int sa = (unsigned int)__cvta_generic_to_shared(s);
  asm volatile("cp.async.cg.shared.global [%0], [%1], 16;\n" :: "r"(sa), "l"(g));
}
#define CP_COMMIT asm volatile("cp.async.commit_group;\n")
#define CP_WAIT(n) asm volatile("cp.async.wait_group %0;\n" :: "n"(n))

__device__ __forceinline__ void mma16816(float* d, const unsigned* a, const unsigned* b){
  asm volatile("mma.sync.aligned.m16n8k16.row.col.f32.bf16.bf16.f32 "
    "{%0,%1,%2,%3},{%4,%5,%6,%7},{%8,%9},{%0,%1,%2,%3};"
    : "+f"(d[0]),"+f"(d[1]),"+f"(d[2]),"+f"(d[3])
    : "r"(a[0]),"r"(a[1]),"r"(a[2]),"r"(a[3]),"r"(b[0]),"r"(b[1]));
}
__device__ __forceinline__ void ldsm4(unsigned* r, unsigned addr){
  asm volatile("ldmatrix.sync.aligned.m8n8.x4.shared.b16 {%0,%1,%2,%3}, [%4];"
    : "=r"(r[0]),"=r"(r[1]),"=r"(r[2]),"=r"(r[3]) : "r"(addr));
}
__device__ __forceinline__ void ldsm4t(unsigned* r, unsigned addr){
  asm volatile("ldmatrix.sync.aligned.m8n8.x4.trans.shared.b16 {%0,%1,%2,%3}, [%4];"
    : "=r"(r[0]),"=r"(r[1]),"=r"(r[2]),"=r"(r[3]) : "r"(addr));
}

// ---------------------------------------------------------------------------
// Weight split-converts
// ---------------------------------------------------------------------------
__global__ void convsplit_kernel(const float* __restrict__ W,
                                 __nv_bfloat16* __restrict__ Wh,
                                 __nv_bfloat16* __restrict__ Wl,
                                 int Kk, int KPp, int total)
{
  int i = blockIdx.x*256 + threadIdx.x;
  if(i >= total) return;
  int r = i / Kk, c = i - r*Kk;
  float x = W[i];
  __nv_bfloat16 h = __float2bfloat16(x);
  Wh[(size_t)r*KPp + c] = h;
  Wl[(size_t)r*KPp + c] = __float2bfloat16(x - __bfloat162float(h));
}

__global__ void convsplit_qkv_kernel(const float* __restrict__ Wq,
                                     const float* __restrict__ Wk,
                                     const float* __restrict__ Wv,
                                     __nv_bfloat16* __restrict__ Wh,
                                     __nv_bfloat16* __restrict__ Wl)
{
  int i = blockIdx.x*256 + threadIdx.x;
  if(i >= 3*D*DH) return;
  int r = i / DH, c = i - r*DH;
  const float* src = (r < D) ? Wq : ((r < 2*D) ? Wk : Wv);
  int rl = (r < D) ? r : ((r < 2*D) ? r - D : r - 2*D);
  float x = src[(size_t)rl*DH + c];
  __nv_bfloat16 h = __float2bfloat16(x);
  Wh[(size_t)r*KP1 + c] = h;
  Wl[(size_t)r*KP1 + c] = __float2bfloat16(x - __bfloat162float(h));
}

// ---------------------------------------------------------------------------
// LayerNorm (+optional add) + add_time -> split planes
// ---------------------------------------------------------------------------
__global__ void ln_addtime_kernel(const float* __restrict__ in1, int ld1, int off1,
                                  const float* __restrict__ in2, int ld2, int off2,
                                  const float* __restrict__ gv, const float* __restrict__ bv,
                                  __nv_bfloat16* __restrict__ outh,
                                  __nv_bfloat16* __restrict__ outl,
                                  float* __restrict__ rawOut)
{
  __shared__ float red[8];
  int row = blockIdx.x, tid = threadIdx.x;
  float v[3];
  #pragma unroll
  for(int q=0;q<3;q++){
    int j = tid + q*256;
    float x = in1[(size_t)row*ld1 + off1 + j];
    if(in2) x += in2[(size_t)row*ld2 + off2 + j];
    v[q] = x;
    if(rawOut) rawOut[(size_t)row*D + j] = x;
  }
  float s  = v[0]+v[1]+v[2];
  float s2 = v[0]*v[0]+v[1]*v[1]+v[2]*v[2];
  s  = blockSum(s,  red);
  float mu = s * (1.f/768.f);
  s2 = blockSum(s2, red);
  float var = s2*(1.f/768.f) - mu*mu;
  float rstd = rsqrtf(var + 1e-5f);
  float w[3]; float n2 = 0.f;
  #pragma unroll
  for(int q=0;q<3;q++){
    int j = tid + q*256;
    w[q] = (v[q]-mu)*rstd*gv[j] + bv[j];
    n2 += w[q]*w[q];
  }
  n2 = blockSum(n2, red);
  #pragma unroll
  for(int q=0;q<3;q++){
    int j = tid + q*256;
    splitStore(outh + (size_t)row*KP1 + 1 + j, outl + (size_t)row*KP1 + 1 + j, w[q]);
  }
  if(tid==0) splitStore(outh + (size_t)row*KP1, outl + (size_t)row*KP1, sqrtf(1.f + n2));
}

// ---------------------------------------------------------------------------
// Tensor-core split-bf16 GEMM: C[M,N] = A[M,K]*B[N,K]^T
//   128x128 CTA tile, BK=32, 16 warps (4x4), 32x32 warp tile,
//   3-stage cp.async pipeline, ldmatrix frags. 512 threads.
// ---------------------------------------------------------------------------
#define HG_STAGE_BF16 20480
#define HG_STAGE_BYTES 40960
#define HG_SMEM_BYTES (3*HG_STAGE_BYTES)

__global__ void __launch_bounds__(512,1) hgemm_kernel(
    const __nv_bfloat16* __restrict__ Ah, const __nv_bfloat16* __restrict__ Al,
    const __nv_bfloat16* __restrict__ Bh, const __nv_bfloat16* __restrict__ Bl,
    float* __restrict__ Cf, __nv_bfloat16* __restrict__ Ch, __nv_bfloat16* __restrict__ Cl,
    int KP, int ldc, int mode)
{
  extern __shared__ __nv_bfloat16 smb[];
  int tid = threadIdx.x;
  int lane = tid & 31, wid = tid >> 5;
  int wm = wid >> 2, wn = wid & 3;
  int g = lane >> 2, t = lane & 3;
  int row0 = blockIdx.y*128, col0 = blockIdx.x*128;

  float acc[2][4][4];
  #pragma unroll
  for(int mi=0;mi<2;mi++)
    #pragma unroll
    for(int ni=0;ni<4;ni++)
      #pragma unroll
      for(int e=0;e<4;e++) acc[mi][ni][e]=0.f;

  const int niter = KP >> 5;
  const unsigned smemU = (unsigned)__cvta_generic_to_shared(smb);

  // A warp band: 32 rows at wm*32; mi in {0,1} covers 16-row MMAs
  const int aRow = wm*32 + (lane&7) + ((lane>>3)&1)*8;
  const int aCol = ((lane>>4)&1)*8;
  const unsigned aOffH = (unsigned)((aRow*40 + aCol)*2);
  // B ldmatrix x4 straddling hi/lo planes
  const int bRow8 = lane & 7;
  const int bSel  = (lane >> 3) & 1;
  const unsigned bOff4 = (unsigned)(20480 + ((bRow8)*40 + bSel*8)*2 + ((lane & 16) ? 10240 : 0));

  // stage loader: 512 threads, 4 cpasync each (one per plane)
  int ldrow = tid >> 2, ldcc = (tid & 3)*8;

  #define LOAD_STAGE(stg, k0) do{                                             \
    __nv_bfloat16* s = smb + (stg)*HG_STAGE_BF16;                             \
    cpasync16(s +          ldrow*40 + ldcc,  Ah + (size_t)(row0+ldrow)*KP + (k0) + ldcc);  \
    cpasync16(s +  5120 +  ldrow*40 + ldcc,  Al + (size_t)(row0+ldrow)*KP + (k0) + ldcc);  \
    cpasync16(s + 10240 +  ldrow*40 + ldcc,  Bh + (size_t)(col0+ldrow)*KP + (k0) + ldcc);  \
    cpasync16(s + 15360 +  ldrow*40 + ldcc,  Bl + (size_t)(col0+ldrow)*KP + (k0) + ldcc);  \
    CP_COMMIT;                                                                \
  } while(0)

  LOAD_STAGE(0, 0);
  LOAD_STAGE(1, 32);

  for(int it=0; it<niter; it++){
    if(it == niter-1){ CP_WAIT(0); } else { CP_WAIT(1); }
    __syncthreads();
    if(it+2 < niter) LOAD_STAGE((it+2)%3, (it+2)<<5);

    const unsigned sb = smemU + (unsigned)((it%3)*HG_STAGE_BYTES);

    #pragma unroll
    for(int ks=0;ks<2;ks++){
      unsigned a_h[2][4], a_l[2][4];
      #pragma unroll
      for(int mi=0;mi<2;mi++){
        unsigned ad = sb + aOffH + (unsigned)(mi*1280 + ks*32);
        ldsm4(a_h[mi], ad);
        ldsm4(a_l[mi], ad + 10240);
      }
      unsigned bhl[4][4];
      #pragma unroll
      for(int ni=0;ni<4;ni++){
        unsigned bd = sb + bOff4 + (unsigned)(wn*2560 + ni*640 + ks*32);
        ldsm4(bhl[ni], bd);
      }
      #pragma unroll
      for(int mi=0;mi<2;mi++)
        #pragma unroll
        for(int ni=0;ni<4;ni++) mma16816(acc[mi][ni], a_h[mi], bhl[ni]);
      #pragma unroll
      for(int mi=0;mi<2;mi++)
        #pragma unroll
        for(int ni=0;ni<4;ni++) mma16816(acc[mi][ni], a_h[mi], bhl[ni]+2);
      #pragma unroll
      for(int mi=0;mi<2;mi++)
        #pragma unroll
        for(int ni=0;ni<4;ni++) mma16816(acc[mi][ni], a_l[mi], bhl[ni]);
    }
  }

  // ---- epilogue ----
  int mat = blockIdx.x / 6;
  int cmatBase = mat*768;
  #pragma unroll
  for(int mi=0;mi<2;mi++){
    int rb = row0 + wm*32 + mi*16 + g;
    #pragma unroll
    for(int ni=0;ni<4;ni++){
      int cb = col0 + wn*32 + ni*8 + 2*t;
      float* a = acc[mi][ni];
      #pragma unroll
      for(int e=0;e<4;e++){
        int r = rb + (e>=2 ? 8 : 0);
        int c = cb + (e&1);
        float v = a[e];
        if(mode==2){
          v = 0.5f*v*(1.f + erff(v*0.70710678118654752f));
          splitStore(Ch + (size_t)r*ldc + c, Cl + (size_t)r*ldc + c, v);
        } else if(mode==1){
          int b_ = r >> 10, ii = r & 1023;
          int cmat = c - cmatBase;
          int h = cmat >> 6, cc2 = cmat & 63;
          Cf[(size_t)mat*(BH*SEQ*HDIM) + (size_t)(((b_*HEADS+h)<<10) + ii)*HDIM + cc2] = v;
        } else {
          Cf[(size_t)r*ldc + c] = v;
        }
      }
    }
  }
}

// ---------------------------------------------------------------------------
// Prep: qt, kt, v->v_tan; Q,K single bf16 planes; V split planes.
// ---------------------------------------------------------------------------
__global__ void prep_kernel()
{
  int w = blockIdx.x*8 + (threadIdx.x>>5);
  int lane = threadIdx.x & 31;

  const float* q = g_QKVf + (size_t)w*HDIM;
  float qv[2]; float s = 0.f;
  #pragma unroll
  for(int e=0;e<2;e++){ qv[e] = q[lane+32*e]; s += qv[e]*qv[e]; }
  s = warpSum(s);
  if(lane==0) g_qt[w] = sqrtf(1.f + s);
  #pragma unroll
  for(int e=0;e<2;e++)
    g_Qsph[(size_t)w*HDIM + lane+32*e] = __float2bfloat16(qv[e]);

  const float* k = g_QKVf + (size_t)(BH*SEQ)*HDIM + (size_t)w*HDIM;
  float kv[2]; s = 0.f;
  #pragma unroll
  for(int e=0;e<2;e++){ kv[e] = k[lane+32*e]; s += kv[e]*kv[e]; }
  s = warpSum(s);
  if(lane==0) g_kt[w] = sqrtf(1.f + s);
  #pragma unroll
  for(int e=0;e<2;e++)
    g_Ksph[(size_t)w*HDIM + lane+32*e] = __float2bfloat16(kv[e]);

  const float* v = g_QKVf + (size_t)(2*BH*SEQ)*HDIM + (size_t)w*HDIM;
  float vv[2]; s = 0.f;
  #pragma unroll
  for(int e=0;e<2;e++){ vv[e] = v[lane+32*e]; s += vv[e]*vv[e]; }
  s = warpSum(s);
  float sn = sqrtf(s);
  float vt = sqrtf(1.f + s);
  float vc = fmaxf(vt, 1.0000001f);
  float dist = __logf(vc + sqrtf((vc-1.f)*(vc+1.f)));
  float scl = dist / fmaxf(sn, 1e-8f);
  #pragma unroll
  for(int e=0;e<2;e++)
    splitStore(g_Vsph + (size_t)w*HDIM + lane+32*e, g_Vspl + (size_t)w*HDIM + lane+32*e, vv[e]*scl);
}

// ---------------------------------------------------------------------------
// Tensor-core fused hyperbolic flash attention (verified R8).
// ---------------------------------------------------------------------------
#define AT_STR   72
#define AT_PLANE (64*AT_STR)
#define AT_STAGE (3*AT_PLANE)
#define AT_SMEM_BYTES (2*AT_STAGE*2 + 2*64*4)

__device__ __forceinline__ float attn_logit(float sv, float qt, float cq, float rsh,
                                            float Bq, float ktj, float lam, float tau,
                                            float spm){
  float rawc = fmaxf(qt*ktj - sv, 1.0f);
  bool selfp = rawc < 1.00001f;
  float c = selfp ? 2.f : rawc;
  float x = (c-1.f)*(c+1.f);
  float rs = rsqrtf(fmaxf(x, 1e-12f));
  float sh = x*rs;
  float dist = __logf(c + sh);
  float ck = fmaxf(ktj, 1.0000001f);
  float Z = (rawc*cq - ck)*rs*rsh;
  Z = selfp ? 1.f : fminf(fmaxf(Z, -1.f), 1.f);
  float pen = -lam*__logf(1.f + dist*dist);
  float ent = __logf(1.f + __expf(Bq + Z - 0.1f)) - spm;
  return pen - tau*ent;
}

__global__ void __launch_bounds__(256,1) attn_kernel(
    const float* __restrict__ alpha_raw,
    const float* __restrict__ tau_raw,
    const float* __restrict__ lambda_raw)
{
  extern __shared__ __nv_bfloat16 smA[];
  float* ktsBuf = (float*)(smA + 2*AT_STAGE);

  const int bh = blockIdx.y;
  const int qrow0 = blockIdx.x*128;
  const int tid = threadIdx.x;
  const int lane = tid & 31, wid = tid >> 5;
  const int g = lane >> 2, t = lane & 3;
  const unsigned smemU = (unsigned)__cvta_generic_to_shared(smA);

  const float alpha = log1pf(expf(alpha_raw[0]));
  const float tau   = log1pf(expf(tau_raw[0]));
  const float lam   = log1pf(expf(lambda_raw[0]));
  const float spm   = log1pf(expf(-0.1f));

  {
    const __nv_bfloat16* gQ = g_Qsph + ((size_t)bh*SEQ + qrow0)*HDIM;
    #pragma unroll
    for(int itn=0; itn<4; itn++){
      int ch = tid + itn*256;
      int r = ch >> 3, c0 = (ch & 7)*8;
      *(uint4*)(smA + r*AT_STR + c0) = *(const uint4*)(gQ + r*HDIM + c0);
    }
  }
  __syncthreads();

  unsigned qh[4][4];
  {
    const unsigned* pQ = (const unsigned*)smA;
    int rbase = wid*16 + g;
    #pragma unroll
    for(int ks=0; ks<4; ks++){
      int base = rbase*(AT_STR/2) + ks*8 + t;
      qh[ks][0]=pQ[base];               qh[ks][1]=pQ[base+8*(AT_STR/2)];
      qh[ks][2]=pQ[base+4];             qh[ks][3]=pQ[base+8*(AT_STR/2)+4];
    }
  }
  __syncthreads();

  const int rowL = qrow0 + wid*16 + g;
  const int rowH = rowL + 8;
  float qtL = g_qt[bh*SEQ + rowL], qtH = g_qt[bh*SEQ + rowH];
  float cqL = fmaxf(qtL, 1.0000001f), cqH = fmaxf(qtH, 1.0000001f);
  float ctL = fminf(__logf(cqL + sqrtf((cqL-1.f)*(cqL+1.f))), 40.f);
  float ctH = fminf(__logf(cqH + sqrtf((cqH-1.f)*(cqH+1.f))), 40.f);
  float rshL = 1.f/sinhf(ctL), rshH = 1.f/sinhf(ctH);
  float BqL = alpha*ctL/(1.f + alpha*ctL);
  float BqH = alpha*ctH/(1.f + alpha*ctH);

  float accO[8][4];
  #pragma unroll
  for(int ni=0;ni<8;ni++)
    #pragma unroll
    for(int e=0;e<4;e++) accO[ni][e]=0.f;
  float lsumL = 0.f, lsumH = 0.f;

  const __nv_bfloat16* gKh = g_Ksph + (size_t)bh*SEQ*HDIM;
  const __nv_bfloat16* gVh = g_Vsph + (size_t)bh*SEQ*HDIM;
  const __nv_bfloat16* gVl = g_Vspl + (size_t)bh*SEQ*HDIM;
  const float* gkt = g_kt + bh*SEQ;

  const int kj = (lane&7) + ((lane>>4)&1)*8;
  const int kd = ((lane>>3)&1)*8;
  const int vj = (lane&7) + ((lane>>3)&1)*8;
  const int vc = ((lane>>4)&1)*8;

  #define AT_LOAD(stg, jb) do{                                                  \
    __nv_bfloat16* s = smA + (stg)*AT_STAGE;                                    \
    _Pragma("unroll")                                                           \
    for(int q_=0;q_<6;q_++){                                                    \
      int ch = tid + q_*256;                                                    \
      int pl = ch >> 9, cw = ch & 511;                                          \
      int r_ = cw >> 3, c_ = (cw & 7)*8;                                        \
      const __nv_bfloat16* src = (pl==0? gKh : (pl==1? gVh : gVl));             \
      cpasync16(s + pl*AT_PLANE + r_*AT_STR + c_,                               \
                src + (size_t)((jb)+r_)*HDIM + c_);                             \
    }                                                                           \
    if(tid < 16) cpasync16(ktsBuf + (stg)*64 + tid*4, gkt + (jb) + tid*4);      \
    CP_COMMIT;                                                                  \
  } while(0)

  AT_LOAD(0, 0);

  for(int jt=0; jt<16; jt++){
    if(jt+1 < 16){ AT_LOAD((jt+1)&1, (jt+1)*64); CP_WAIT(1); }
    else         { CP_WAIT(0); }
    __syncthreads();

    const unsigned sbK = smemU + (unsigned)(((jt&1)*AT_STAGE)*2);
    const unsigned sbVh = sbK + (unsigned)(AT_PLANE*2);
    const unsigned sbVl = sbK + (unsigned)(2*AT_PLANE*2);
    const float* kts = ktsBuf + (jt&1)*64;

    float accS[8][4];
    #pragma unroll
    for(int ni=0;ni<8;ni++)
      #pragma unroll
      for(int e=0;e<4;e++) accS[ni][e]=0.f;

    #pragma unroll
    for(int ks=0; ks<4; ks++){
      #pragma unroll
      for(int np=0; np<4; np++){
        unsigned kb[4];
        unsigned ad = sbK + (unsigned)(((np*16 + kj)*AT_STR + ks*16 + kd)*2);
        ldsm4(kb, ad);
        mma16816(accS[2*np],   qh[ks], kb);
        mma16816(accS[2*np+1], qh[ks], kb+2);
      }
    }

    #pragma unroll
    for(int ni=0; ni<8; ni++){
      float2 ktp = *(const float2*)&kts[ni*8 + 2*t];
      float z0 = attn_logit(accS[ni][0], qtL, cqL, rshL, BqL, ktp.x, lam, tau, spm);
      float z1 = attn_logit(accS[ni][1], qtL, cqL, rshL, BqL, ktp.y, lam, tau, spm);
      float z2 = attn_logit(accS[ni][2], qtH, cqH, rshH, BqH, ktp.x, lam, tau, spm);
      float z3 = attn_logit(accS[ni][3], qtH, cqH, rshH, BqH, ktp.y, lam, tau, spm);
      float p0 = __expf(z0), p1 = __expf(z1), p2 = __expf(z2), p3 = __expf(z3);
      lsumL += p0 + p1;
      lsumH += p2 + p3;
      accS[ni][0]=p0; accS[ni][1]=p1; accS[ni][2]=p2; accS[ni][3]=p3;
    }

    #pragma unroll
    for(int kc=0; kc<4; kc++){
      unsigned aP[4];
      packhi(accS[2*kc  ][0], accS[2*kc  ][1], aP[0]);
      packhi(accS[2*kc  ][2], accS[2*kc  ][3], aP[1]);
      packhi(accS[2*kc+1][0], accS[2*kc+1][1], aP[2]);
      packhi(accS[2*kc+1][2], accS[2*kc+1][3], aP[3]);
      #pragma unroll
      for(int nq=0; nq<4; nq++){
        unsigned voff = (unsigned)(((kc*16 + vj)*AT_STR + nq*16 + vc)*2);
        unsigned vb[4], vlb[4];
        ldsm4t(vb,  sbVh + voff);
        ldsm4t(vlb, sbVl + voff);
        mma16816(accO[2*nq],   aP, vb);
        mma16816(accO[2*nq+1], aP, vb+2);
        mma16816(accO[2*nq],   aP, vlb);
        mma16816(accO[2*nq+1], aP, vlb+2);
      }
    }
    __syncthreads();
  }

  float lL = lsumL, lH = lsumH;
  #pragma unroll
  for(int o=1;o<4;o<<=1){
    lL += __shfl_xor_sync(0xffffffffu, lL, o);
    lH += __shfl_xor_sync(0xffffffffu, lH, o);
  }
  float invL = 1.f/(lL*(1.f + 1e-8f));
  float invH = 1.f/(lH*(1.f + 1e-8f));

  float agL[8][2], agH[8][2];
  float nnL = 0.f, nnH = 0.f;
  #pragma unroll
  for(int ni=0;ni<8;ni++){
    agL[ni][0] = accO[ni][0]*invL; agL[ni][1] = accO[ni][1]*invL;
    agH[ni][0] = accO[ni][2]*invH; agH[ni][1] = accO[ni][3]*invH;
    nnL += agL[ni][0]*agL[ni][0] + agL[ni][1]*agL[ni][1];
    nnH += agH[ni][0]*agH[ni][0] + agH[ni][1]*agH[ni][1];
  }
  #pragma unroll
  for(int o=1;o<4;o<<=1){
    nnL += __shfl_xor_sync(0xffffffffu, nnL, o);
    nnH += __shfl_xor_sync(0xffffffffu, nnH, o);
  }
  nnL = sqrtf(nnL); nnH = sqrtf(nnH);
  float tL = coshf(nnL), tH = coshf(nnH);
  float sclL = sinhf(nnL)/fmaxf(nnL, 1e-8f);
  float sclH = sinhf(nnH)/fmaxf(nnH, 1e-8f);

  const int b_ = bh / HEADS, h = bh % HEADS;
  const int growL = b_*SEQ + rowL, growH = b_*SEQ + rowH;
  #pragma unroll
  for(int ni=0;ni<8;ni++){
    int c0 = ni*8 + 2*t;
    size_t iL = (size_t)growL*KP1 + 1 + h*HDIM + c0;
    size_t iH = (size_t)growH*KP1 + 1 + h*HDIM + c0;
    splitStore(g_AINh + iL,     g_AINl + iL,     agL[ni][0]*sclL);
    splitStore(g_AINh + iL + 1, g_AINl + iL + 1, agL[ni][1]*sclL);
    splitStore(g_AINh + iH,     g_AINl + iH,     agH[ni][0]*sclH);
    splitStore(g_AINh + iH + 1, g_AINl + iH + 1, agH[ni][1]*sclH);
  }
  if(t==0){
    g_Th[growL*HEADS + h] = tL;
    g_Th[growH*HEADS + h] = tH;
  }
}

// t_new
__global__ void tnew_kernel()
{
  int r = blockIdx.x*256 + threadIdx.x;
  if(r >= ROWS) return;
  float s = 0.f;
  #pragma unroll
  for(int h=0; h<HEADS; h++){ float t = g_Th[r*HEADS+h]; s += t*t; }
  splitStore(g_AINh + (size_t)r*KP1, g_AINl + (size_t)r*KP1, sqrtf(s - (float)(HEADS-1)));
}

// time col for mlp hidden
__global__ void time_mlp_kernel()
{
  __shared__ float red[8];
  int row = blockIdx.x, tid = threadIdx.x;
  float s = 0.f;
  #pragma unroll
  for(int q=0;q<12;q++){
    size_t idx = (size_t)row*KP2 + 1 + tid + q*256;
    float x = __bfloat162float(g_H1h[idx]) + __bfloat162float(g_H1l[idx]);
    s += x*x;
  }
  s = blockSum(s, red);
  if(tid==0) splitStore(g_H1h + (size_t)row*KP2, g_H1l + (size_t)row*KP2, sqrtf(1.f + s));
}

// final
__global__ void final_kernel(float* __restrict__ out)
{
  __shared__ float red[8];
  int row = blockIdx.x, tid = threadIdx.x;
  float v[3]; float s = 0.f;
  #pragma unroll
  for(int q=0;q<3;q++){
    int j = tid + q*256;
    float x = g_G2[(size_t)row*D + j] + g_OUT[(size_t)row*D + j];
    v[q] = x; s += x*x;
  }
  s = blockSum(s, red);
  #pragma unroll
  for(int q=0;q<3;q++){
    int j = tid + q*256;
    out[(size_t)row*DH + 1 + j] = v[q];
  }
  if(tid==0) out[(size_t)row*DH] = sqrtf(1.f + s);
}

// ---------------------------------------------------------------------------
// Launch
// ---------------------------------------------------------------------------
extern "C" void kernel_launch(void* const* d_in, const int* in_sizes, int n_in,
                              void* d_out, int out_size)
{
  const float* x    = (const float*)d_in[0];
  const float* Wq   = (const float*)d_in[1];
  const float* Wk   = (const float*)d_in[2];
  const float* Wv   = (const float*)d_in[3];
  const float* Wo   = (const float*)d_in[4];
  const float* ln1g = (const float*)d_in[5];
  const float* ln1b = (const float*)d_in[6];
  const float* ln2g = (const float*)d_in[7];
  const float* ln2b = (const float*)d_in[8];
  const float* Wm1  = (const float*)d_in[9];
  const float* Wm2  = (const float*)d_in[10];
  const float* araw = (const float*)d_in[11];
  const float* traw = (const float*)d_in[12];
  const float* lraw = (const float*)d_in[13];
  float* out = (float*)d_out;

  float *pQKV, *pMO, *pOUT, *pG2;
  cudaGetSymbolAddress((void**)&pQKV, g_QKVf);
  cudaGetSymbolAddress((void**)&pMO,  g_MO);
  cudaGetSymbolAddress((void**)&pOUT, g_OUT);
  cudaGetSymbolAddress((void**)&pG2,  g_G2);

  __nv_bfloat16 *pX1h,*pX1l,*pAINh,*pAINl,*pHh,*pHl,*pH1h,*pH1l;
  __nv_bfloat16 *pWqkvh,*pWqkvl,*pWoh,*pWol,*pW1h,*pW1l,*pW2h,*pW2l;
  cudaGetSymbolAddress((void**)&pX1h,  g_X1h);  cudaGetSymbolAddress((void**)&pX1l,  g_X1l);
  cudaGetSymbolAddress((void**)&pAINh, g_AINh); cudaGetSymbolAddress((void**)&pAINl, g_AINl);
  cudaGetSymbolAddress((void**)&pHh,   g_Hh);   cudaGetSymbolAddress((void**)&pHl,   g_Hl);
  cudaGetSymbolAddress((void**)&pH1h,  g_H1h);  cudaGetSymbolAddress((void**)&pH1l,  g_H1l);
  cudaGetSymbolAddress((void**)&pWqkvh,g_Wqkvh);cudaGetSymbolAddress((void**)&pWqkvl,g_Wqkvl);
  cudaGetSymbolAddress((void**)&pWoh,  g_Woh);  cudaGetSymbolAddress((void**)&pWol,  g_Wol);
  cudaGetSymbolAddress((void**)&pW1h,  g_W1h);  cudaGetSymbolAddress((void**)&pW1l,  g_W1l);
  cudaGetSymbolAddress((void**)&pW2h,  g_W2h);  cudaGetSymbolAddress((void**)&pW2l,  g_W2l);

  cudaFuncSetAttribute(hgemm_kernel, cudaFuncAttributeMaxDynamicSharedMemorySize,
                       HG_SMEM_BYTES);
  cudaFuncSetAttribute(attn_kernel, cudaFuncAttributeMaxDynamicSharedMemorySize,
                       AT_SMEM_BYTES);

  // 0,1: weight converts needed before QKV/Wo GEMMs
  {
    int tq = 3*D*DH;
    convsplit_qkv_kernel<<<(tq+255)/256,256>>>(Wq, Wk, Wv, pWqkvh, pWqkvl);
    int t1 = D*DH;
    convsplit_kernel<<<(t1+255)/256,256>>>(Wo, pWoh, pWol, DH, KP1, t1);
  }

  // 2: ln1 + add_time
  ln_addtime_kernel<<<ROWS,256>>>(x, DH, 1, nullptr, 0, 0, ln1g, ln1b, pX1h, pX1l, nullptr);

  // 3: fused QKV projection
  dim3 gqkv(2304/128, ROWS/128);
  hgemm_kernel<<<gqkv,512,HG_SMEM_BYTES>>>(pX1h,pX1l, pWqkvh,pWqkvl, pQKV,nullptr,nullptr, KP1, 0, 1);

  // 4: prep
  prep_kernel<<<(BH*SEQ)/8, 256>>>();

  // 5: fused attention
  attn_kernel<<<dim3(SEQ/128, BH), 256, AT_SMEM_BYTES>>>(araw, traw, lraw);

  // 6: t_new
  tnew_kernel<<<ROWS/256, 256>>>();

  // 7: Wm1 convert (deferred)
  {
    int t2 = DM*DH;
    convsplit_kernel<<<(t2+255)/256,256>>>(Wm1, pW1h, pW1l, DH, KP1, t2);
  }

  // 8: Wo projection
  dim3 g768(D/128, ROWS/128);
  hgemm_kernel<<<g768,512,HG_SMEM_BYTES>>>(pAINh,pAINl, pWoh,pWol, pMO,nullptr,nullptr, KP1, D, 0);

  // 9: residual + ln2
  ln_addtime_kernel<<<ROWS,256>>>(pMO, D, 0, x, DH, 1, ln2g, ln2b, pHh, pHl, pOUT);

  // 10: MLP up with gelu
  dim3 g3072(DM/128, ROWS/128);
  hgemm_kernel<<<g3072,512,HG_SMEM_BYTES>>>(pHh,pHl, pW1h,pW1l, nullptr, pH1h+1, pH1l+1, KP1, KP2, 2);

  // 11: Wm2 convert (deferred)
  {
    int t3 = D*DMH;
    convsplit_kernel<<<(t3+255)/256,256>>>(Wm2, pW2h, pW2l, DMH, KP2, t3);
  }

  // 12: mlp hidden time col
  time_mlp_kernel<<<ROWS,256>>>();

  // 13: MLP down
  hgemm_kernel<<<g768,512,HG_SMEM_BYTES>>>(pH1h,pH1l, pW2h,pW2l, pG2,nullptr,nullptr, KP2, D, 0);

  // 14: final
  final_kernel<<<ROWS,256>>>(out);
}

// round 12
// speedup vs baseline: 1.3831x; 1.3831x over previous
#include <cuda_runtime.h>
#include <cuda_bf16.h>
#include <cuda_fp16.h>
#include <math.h>
#include <cstdint>

// ---------------------------------------------------------------------------
// Problem constants
// ---------------------------------------------------------------------------
#define BATCH 4
#define SEQ   1024
#define D     768
#define DH    769
#define HEADS 12
#define HDIM  64
#define BH    (BATCH*HEADS)      // 48
#define ROWS  (BATCH*SEQ)        // 4096
#define DM    3072
#define DMH   3073
#define KP1   800
#define KP2   3104

// ---------------------------------------------------------------------------
// Scratch
// ---------------------------------------------------------------------------
__device__ float g_QKVf[3*BH*SEQ*HDIM];
__device__ float g_qt [BH*SEQ];
__device__ float g_kt [BH*SEQ];
__device__ float g_Th [ROWS*HEADS];
__device__ float g_MO [ROWS*D];
__device__ float g_OUT[ROWS*D];
__device__ float g_G2 [ROWS*D];

// bf16 per-head planes for attention (Q,K single; V split) -- verified path
__device__ __nv_bfloat16 g_Qsph[BH*SEQ*HDIM];
__device__ __nv_bfloat16 g_Ksph[BH*SEQ*HDIM];
__device__ __nv_bfloat16 g_Vsph[BH*SEQ*HDIM], g_Vspl[BH*SEQ*HDIM];

// fp16 single-plane activations (GEMM A operands)
__device__ __half g_X1f [ROWS*KP1];
__device__ __half g_AINf[ROWS*KP1];
__device__ __half g_Hf  [ROWS*KP1];
__device__ __half g_H1f [ROWS*KP2];

// fp16 split weight planes (GEMM B operands)
__device__ __half g_Wqkvh[3*D*KP1], g_Wqkvl[3*D*KP1];
__device__ __half g_Woh[D*KP1],  g_Wol[D*KP1];
__device__ __half g_W1h[DM*KP1], g_W1l[DM*KP1];
__device__ __half g_W2h[D*KP2],  g_W2l[D*KP2];

// ---------------------------------------------------------------------------
// Helpers
// ---------------------------------------------------------------------------
__device__ __forceinline__ float warpSum(float v){
  #pragma unroll
  for(int o=16;o>0;o>>=1) v += __shfl_xor_sync(0xffffffffu, v, o);
  return v;
}
__device__ __forceinline__ float blockSum(float v, float* sh){
  int lane = threadIdx.x & 31, w = threadIdx.x >> 5;
  v = warpSum(v);
  if(lane==0) sh[w] = v;
  __syncthreads();
  float r = (threadIdx.x < 8) ? sh[threadIdx.x] : 0.f;
  if(w==0) r = warpSum(r);
  if(threadIdx.x==0) sh[0] = r;
  __syncthreads();
  r = sh[0];
  __syncthreads();
  return r;
}
__device__ __forceinline__ void splitStoreBf(__nv_bfloat16* ph, __nv_bfloat16* pl, float x){
  __nv_bfloat16 h = __float2bfloat16(x);
  *ph = h;
  *pl = __float2bfloat16(x - __bfloat162float(h));
}
__device__ __forceinline__ void splitStoreHf(__half* ph, __half* pl, float x){
  __half h = __float2half(x);
  *ph = h;
  *pl = __float2half(x - __half2float(h));
}
__device__ __forceinline__ void packhi(float a, float b, unsigned &h){
  __nv_bfloat162 hp; hp.x = __float2bfloat16(a); hp.y = __float2bfloat16(b);
  h = *(unsigned*)&hp;
}
__device__ __forceinline__ void cpasync16(void* s, const void* g){
  unsigned int sa = (unsigned int)__cvta_generic_to_shared(s);
  asm volatile("cp.async.cg.shared.global [%0], [%1], 16;\n" :: "r"(sa), "l"(g));
}
#define CP_COMMIT asm volatile("cp.async.commit_group;\n")
#define CP_WAIT(n) asm volatile("cp.async.wait_group %0;\n" :: "n"(n))

__device__ __forceinline__ void mma16816bf(float* d, const unsigned* a, const unsigned* b){
  asm volatile("mma.sync.aligned.m16n8k16.row.col.f32.bf16.bf16.f32 "
    "{%0,%1,%2,%3},{%4,%5,%6,%7},{%8,%9},{%0,%1,%2,%3};"
    : "+f"(d[0]),"+f"(d[1]),"+f"(d[2]),"+f"(d[3])
    : "r"(a[0]),"r"(a[1]),"r"(a[2]),"r"(a[3]),"r"(b[0]),"r"(b[1]));
}
__device__ __forceinline__ void mma16816hf(float* d, const unsigned* a, const unsigned* b){
  asm volatile("mma.sync.aligned.m16n8k16.row.col.f32.f16.f16.f32 "
    "{%0,%1,%2,%3},{%4,%5,%6,%7},{%8,%9},{%0,%1,%2,%3};"
    : "+f"(d[0]),"+f"(d[1]),"+f"(d[2]),"+f"(d[3])
    : "r"(a[0]),"r"(a[1]),"r"(a[2]),"r"(a[3]),"r"(b[0]),"r"(b[1]));
}
__device__ __forceinline__ void ldsm4(unsigned* r, unsigned addr){
  asm volatile("ldmatrix.sync.aligned.m8n8.x4.shared.b16 {%0,%1,%2,%3}, [%4];"
    : "=r"(r[0]),"=r"(r[1]),"=r"(r[2]),"=r"(r[3]) : "r"(addr));
}
__device__ __forceinline__ void ldsm4t(unsigned* r, unsigned addr){
  asm volatile("ldmatrix.sync.aligned.m8n8.x4.trans.shared.b16 {%0,%1,%2,%3}, [%4];"
    : "=r"(r[0]),"=r"(r[1]),"=r"(r[2]),"=r"(r[3]) : "r"(addr));
}

// ---------------------------------------------------------------------------
// Weight split-converts (fp16 hi/lo)
// ---------------------------------------------------------------------------
__global__ void convsplit_kernel(const float* __restrict__ W,
                                 __half* __restrict__ Wh,
                                 __half* __restrict__ Wl,
                                 int Kk, int KPp, int total)
{
  int i = blockIdx.x*256 + threadIdx.x;
  if(i >= total) return;
  int r = i / Kk, c = i - r*Kk;
  splitStoreHf(Wh + (size_t)r*KPp + c, Wl + (size_t)r*KPp + c, W[i]);
}

__global__ void convsplit_qkv_kernel(const float* __restrict__ Wq,
                                     const float* __restrict__ Wk,
                                     const float* __restrict__ Wv,
                                     __half* __restrict__ Wh,
                                     __half* __restrict__ Wl)
{
  int i = blockIdx.x*256 + threadIdx.x;
  if(i >= 3*D*DH) return;
  int r = i / DH, c = i - r*DH;
  const float* src = (r < D) ? Wq : ((r < 2*D) ? Wk : Wv);
  int rl = (r < D) ? r : ((r < 2*D) ? r - D : r - 2*D);
  splitStoreHf(Wh + (size_t)r*KP1 + c, Wl + (size_t)r*KP1 + c, src[(size_t)rl*DH + c]);
}

// ---------------------------------------------------------------------------
// LayerNorm (+optional add) + add_time -> single fp16 plane
// ---------------------------------------------------------------------------
__global__ void ln_addtime_kernel(const float* __restrict__ in1, int ld1, int off1,
                                  const float* __restrict__ in2, int ld2, int off2,
                                  const float* __restrict__ gv, const float* __restrict__ bv,
                                  __half* __restrict__ outp,
                                  float* __restrict__ rawOut)
{
  __shared__ float red[8];
  int row = blockIdx.x, tid = threadIdx.x;
  float v[3];
  #pragma unroll
  for(int q=0;q<3;q++){
    int j = tid + q*256;
    float x = in1[(size_t)row*ld1 + off1 + j];
    if(in2) x += in2[(size_t)row*ld2 + off2 + j];
    v[q] = x;
    if(rawOut) rawOut[(size_t)row*D + j] = x;
  }
  float s  = v[0]+v[1]+v[2];
  float s2 = v[0]*v[0]+v[1]*v[1]+v[2]*v[2];
  s  = blockSum(s,  red);
  float mu = s * (1.f/768.f);
  s2 = blockSum(s2, red);
  float var = s2*(1.f/768.f) - mu*mu;
  float rstd = rsqrtf(var + 1e-5f);
  float w[3]; float n2 = 0.f;
  #pragma unroll
  for(int q=0;q<3;q++){
    int j = tid + q*256;
    w[q] = (v[q]-mu)*rstd*gv[j] + bv[j];
    n2 += w[q]*w[q];
  }
  n2 = blockSum(n2, red);
  #pragma unroll
  for(int q=0;q<3;q++){
    int j = tid + q*256;
    outp[(size_t)row*KP1 + 1 + j] = __float2half(w[q]);
  }
  if(tid==0) outp[(size_t)row*KP1] = __float2half(sqrtf(1.f + n2));
}

// ---------------------------------------------------------------------------
// fp16 2-term GEMM: C[M,N] = A[M,K]*(Bh+Bl)[N,K]^T
//   128x128 CTA tile, BK=32, 16 warps (4x4), 32x32 warp tile, 512 threads,
//   3-stage cp.async pipeline, ldmatrix frags. 3 smem planes: A | Bh | Bl.
//   mode 0: fp32 out; 1: fused-QKV head-scatter; 2: gelu + fp16 out.
// ---------------------------------------------------------------------------
#define HG_PLANE_H  5120                 // halves per plane (128*40)
#define HG_STAGE_H  (3*HG_PLANE_H)       // 15360 halves
#define HG_STAGE_BYTES (HG_STAGE_H*2)    // 30720
#define HG_SMEM_BYTES (3*HG_STAGE_BYTES) // 92160

__global__ void __launch_bounds__(512,1) hgemm_kernel(
    const __half* __restrict__ Ah,
    const __half* __restrict__ Bh, const __half* __restrict__ Bl,
    float* __restrict__ Cf, __half* __restrict__ Ch,
    int KP, int ldc, int mode)
{
  extern __shared__ __half smb[];
  int tid = threadIdx.x;
  int lane = tid & 31, wid = tid >> 5;
  int wm = wid >> 2, wn = wid & 3;
  int g = lane >> 2, t = lane & 3;
  int row0 = blockIdx.y*128, col0 = blockIdx.x*128;

  float acc[2][4][4];
  #pragma unroll
  for(int mi=0;mi<2;mi++)
    #pragma unroll
    for(int ni=0;ni<4;ni++)
      #pragma unroll
      for(int e=0;e<4;e++) acc[mi][ni][e]=0.f;

  const int niter = KP >> 5;
  const unsigned smemU = (unsigned)__cvta_generic_to_shared(smb);

  const int aRow = wm*32 + (lane&7) + ((lane>>3)&1)*8;
  const int aCol = ((lane>>4)&1)*8;
  const unsigned aOffH = (unsigned)((aRow*40 + aCol)*2);
  // B hi plane at halves 5120 (bytes 10240); lo plane +10240 bytes
  const int bRow8 = lane & 7;
  const int bSel  = (lane >> 3) & 1;
  const unsigned bOff4 = (unsigned)(10240 + ((bRow8)*40 + bSel*8)*2 + ((lane & 16) ? 10240 : 0));

  #define LOAD_STAGE(stg, k0) do{                                             \
    __half* s = smb + (stg)*HG_STAGE_H;                                       \
    _Pragma("unroll")                                                         \
    for(int q_=0;q_<3;q_++){                                                  \
      int idx_ = tid + q_*512;                                                \
      int p_ = idx_ >> 9, w_ = idx_ & 511;                                    \
      int r_ = w_ >> 2, cc_ = (w_ & 3)*8;                                     \
      const __half* src_ = (p_==0? Ah : (p_==1? Bh : Bl));                    \
      int grow_ = (p_==0? row0 : col0) + r_;                                  \
      cpasync16(s + p_*HG_PLANE_H + r_*40 + cc_,                              \
                src_ + (size_t)grow_*KP + (k0) + cc_);                        \
    }                                                                         \
    CP_COMMIT;                                                                \
  } while(0)

  LOAD_STAGE(0, 0);
  LOAD_STAGE(1, 32);

  for(int it=0; it<niter; it++){
    if(it == niter-1){ CP_WAIT(0); } else { CP_WAIT(1); }
    __syncthreads();
    if(it+2 < niter) LOAD_STAGE((it+2)%3, (it+2)<<5);

    const unsigned sb = smemU + (unsigned)((it%3)*HG_STAGE_BYTES);

    #pragma unroll
    for(int ks=0;ks<2;ks++){
      unsigned a_h[2][4];
      #pragma unroll
      for(int mi=0;mi<2;mi++){
        unsigned ad = sb + aOffH + (unsigned)(mi*1280 + ks*32);
        ldsm4(a_h[mi], ad);
      }
      unsigned bhl[4][4];   // per ni: {bh0,bh1,bl0,bl1}
      #pragma unroll
      for(int ni=0;ni<4;ni++){
        unsigned bd = sb + bOff4 + (unsigned)(wn*2560 + ni*640 + ks*32);
        ldsm4(bhl[ni], bd);
      }
      #pragma unroll
      for(int mi=0;mi<2;mi++)
        #pragma unroll
        for(int ni=0;ni<4;ni++) mma16816hf(acc[mi][ni], a_h[mi], bhl[ni]);
      #pragma unroll
      for(int mi=0;mi<2;mi++)
        #pragma unroll
        for(int ni=0;ni<4;ni++) mma16816hf(acc[mi][ni], a_h[mi], bhl[ni]+2);
    }
  }

  // ---- epilogue ----
  int mat = blockIdx.x / 6;
  int cmatBase = mat*768;
  #pragma unroll
  for(int mi=0;mi<2;mi++){
    int rb = row0 + wm*32 + mi*16 + g;
    #pragma unroll
    for(int ni=0;ni<4;ni++){
      int cb = col0 + wn*32 + ni*8 + 2*t;
      float* a = acc[mi][ni];
      #pragma unroll
      for(int e=0;e<4;e++){
        int r = rb + (e>=2 ? 8 : 0);
        int c = cb + (e&1);
        float v = a[e];
        if(mode==2){
          v = 0.5f*v*(1.f + erff(v*0.70710678118654752f));
          Ch[(size_t)r*ldc + c] = __float2half(v);
        } else if(mode==1){
          int b_ = r >> 10, ii = r & 1023;
          int cmat = c - cmatBase;
          int h = cmat >> 6, cc2 = cmat & 63;
          Cf[(size_t)mat*(BH*SEQ*HDIM) + (size_t)(((b_*HEADS+h)<<10) + ii)*HDIM + cc2] = v;
        } else {
          Cf[(size_t)r*ldc + c] = v;
        }
      }
    }
  }
}

// ---------------------------------------------------------------------------
// Prep: qt, kt, v->v_tan; Q,K single bf16 planes; V split planes.
// ---------------------------------------------------------------------------
__global__ void prep_kernel()
{
  int w = blockIdx.x*8 + (threadIdx.x>>5);
  int lane = threadIdx.x & 31;

  const float* q = g_QKVf + (size_t)w*HDIM;
  float qv[2]; float s = 0.f;
  #pragma unroll
  for(int e=0;e<2;e++){ qv[e] = q[lane+32*e]; s += qv[e]*qv[e]; }
  s = warpSum(s);
  if(lane==0) g_qt[w] = sqrtf(1.f + s);
  #pragma unroll
  for(int e=0;e<2;e++)
    g_Qsph[(size_t)w*HDIM + lane+32*e] = __float2bfloat16(qv[e]);

  const float* k = g_QKVf + (size_t)(BH*SEQ)*HDIM + (size_t)w*HDIM;
  float kv[2]; s = 0.f;
  #pragma unroll
  for(int e=0;e<2;e++){ kv[e] = k[lane+32*e]; s += kv[e]*kv[e]; }
  s = warpSum(s);
  if(lane==0) g_kt[w] = sqrtf(1.f + s);
  #pragma unroll
  for(int e=0;e<2;e++)
    g_Ksph[(size_t)w*HDIM + lane+32*e] = __float2bfloat16(kv[e]);

  const float* v = g_QKVf + (size_t)(2*BH*SEQ)*HDIM + (size_t)w*HDIM;
  float vv[2]; s = 0.f;
  #pragma unroll
  for(int e=0;e<2;e++){ vv[e] = v[lane+32*e]; s += vv[e]*vv[e]; }
  s = warpSum(s);
  float sn = sqrtf(s);
  float vt = sqrtf(1.f + s);
  float vc = fmaxf(vt, 1.0000001f);
  float dist = __logf(vc + sqrtf((vc-1.f)*(vc+1.f)));
  float scl = dist / fmaxf(sn, 1e-8f);
  #pragma unroll
  for(int e=0;e<2;e++)
    splitStoreBf(g_Vsph + (size_t)w*HDIM + lane+32*e, g_Vspl + (size_t)w*HDIM + lane+32*e, vv[e]*scl);
}

// ---------------------------------------------------------------------------
// Tensor-core fused hyperbolic flash attention (verified R8/R9 numerics).
// Epilogue writes AIN as single fp16 plane.
// ---------------------------------------------------------------------------
#define AT_STR   72
#define AT_PLANE (64*AT_STR)
#define AT_STAGE (3*AT_PLANE)
#define AT_SMEM_BYTES (2*AT_STAGE*2 + 2*64*4)

__device__ __forceinline__ float attn_logit(float sv, float qt, float cq, float rsh,
                                            float Bq, float ktj, float lam, float tau,
                                            float spm){
  float rawc = fmaxf(qt*ktj - sv, 1.0f);
  bool selfp = rawc < 1.00001f;
  float c = selfp ? 2.f : rawc;
  float x = (c-1.f)*(c+1.f);
  float rs = rsqrtf(fmaxf(x, 1e-12f));
  float sh = x*rs;
  float dist = __logf(c + sh);
  float ck = fmaxf(ktj, 1.0000001f);
  float Z = (rawc*cq - ck)*rs*rsh;
  Z = selfp ? 1.f : fminf(fmaxf(Z, -1.f), 1.f);
  float pen = -lam*__logf(1.f + dist*dist);
  float ent = __logf(1.f + __expf(Bq + Z - 0.1f)) - spm;
  return pen - tau*ent;
}

__global__ void __launch_bounds__(256,1) attn_kernel(
    const float* __restrict__ alpha_raw,
    const float* __restrict__ tau_raw,
    const float* __restrict__ lambda_raw)
{
  extern __shared__ __nv_bfloat16 smA[];
  float* ktsBuf = (float*)(smA + 2*AT_STAGE);

  const int bh = blockIdx.y;
  const int qrow0 = blockIdx.x*128;
  const int tid = threadIdx.x;
  const int lane = tid & 31, wid = tid >> 5;
  const int g = lane >> 2, t = lane & 3;
  const unsigned smemU = (unsigned)__cvta_generic_to_shared(smA);

  const float alpha = log1pf(expf(alpha_raw[0]));
  const float tau   = log1pf(expf(tau_raw[0]));
  const float lam   = log1pf(expf(lambda_raw[0]));
  const float spm   = log1pf(expf(-0.1f));

  {
    const __nv_bfloat16* gQ = g_Qsph + ((size_t)bh*SEQ + qrow0)*HDIM;
    #pragma unroll
    for(int itn=0; itn<4; itn++){
      int ch = tid + itn*256;
      int r = ch >> 3, c0 = (ch & 7)*8;
      *(uint4*)(smA + r*AT_STR + c0) = *(const uint4*)(gQ + r*HDIM + c0);
    }
  }
  __syncthreads();

  unsigned qh[4][4];
  {
    const unsigned* pQ = (const unsigned*)smA;
    int rbase = wid*16 + g;
    #pragma unroll
    for(int ks=0; ks<4; ks++){
      int base = rbase*(AT_STR/2) + ks*8 + t;
      qh[ks][0]=pQ[base];               qh[ks][1]=pQ[base+8*(AT_STR/2)];
      qh[ks][2]=pQ[base+4];             qh[ks][3]=pQ[base+8*(AT_STR/2)+4];
    }
  }
  __syncthreads();

  const int rowL = qrow0 + wid*16 + g;
  const int rowH = rowL + 8;
  float qtL = g_qt[bh*SEQ + rowL], qtH = g_qt[bh*SEQ + rowH];
  float cqL = fmaxf(qtL, 1.0000001f), cqH = fmaxf(qtH, 1.0000001f);
  float ctL = fminf(__logf(cqL + sqrtf((cqL-1.f)*(cqL+1.f))), 40.f);
  float ctH = fminf(__logf(cqH + sqrtf((cqH-1.f)*(cqH+1.f))), 40.f);
  float rshL = 1.f/sinhf(ctL), rshH = 1.f/sinhf(ctH);
  float BqL = alpha*ctL/(1.f + alpha*ctL);
  float BqH = alpha*ctH/(1.f + alpha*ctH);

  float accO[8][4];
  #pragma unroll
  for(int ni=0;ni<8;ni++)
    #pragma unroll
    for(int e=0;e<4;e++) accO[ni][e]=0.f;
  float lsumL = 0.f, lsumH = 0.f;

  const __nv_bfloat16* gKh = g_Ksph + (size_t)bh*SEQ*HDIM;
  const __nv_bfloat16* gVh = g_Vsph + (size_t)bh*SEQ*HDIM;
  const __nv_bfloat16* gVl = g_Vspl + (size_t)bh*SEQ*HDIM;
  const float* gkt = g_kt + bh*SEQ;

  const int kj = (lane&7) + ((lane>>4)&1)*8;
  const int kd = ((lane>>3)&1)*8;
  const int vj = (lane&7) + ((lane>>3)&1)*8;
  const int vc = ((lane>>4)&1)*8;

  #define AT_LOAD(stg, jb) do{                                                  \
    __nv_bfloat16* s = smA + (stg)*AT_STAGE;                                    \
    _Pragma("unroll")                                                           \
    for(int q_=0;q_<6;q_++){                                                    \
      int ch = tid + q_*256;                                                    \
      int pl = ch >> 9, cw = ch & 511;                                          \
      int r_ = cw >> 3, c_ = (cw & 7)*8;                                        \
      const __nv_bfloat16* src = (pl==0? gKh : (pl==1? gVh : gVl));             \
      cpasync16(s + pl*AT_PLANE + r_*AT_STR + c_,                               \
                src + (size_t)((jb)+r_)*HDIM + c_);                             \
    }                                                                           \
    if(tid < 16) cpasync16(ktsBuf + (stg)*64 + tid*4, gkt + (jb) + tid*4);      \
    CP_COMMIT;                                                                  \
  } while(0)

  AT_LOAD(0, 0);

  for(int jt=0; jt<16; jt++){
    if(jt+1 < 16){ AT_LOAD((jt+1)&1, (jt+1)*64); CP_WAIT(1); }
    else         { CP_WAIT(0); }
    __syncthreads();

    const unsigned sbK = smemU + (unsigned)(((jt&1)*AT_STAGE)*2);
    const unsigned sbVh = sbK + (unsigned)(AT_PLANE*2);
    const unsigned sbVl = sbK + (unsigned)(2*AT_PLANE*2);
    const float* kts = ktsBuf + (jt&1)*64;

    float accS[8][4];
    #pragma unroll
    for(int ni=0;ni<8;ni++)
      #pragma unroll
      for(int e=0;e<4;e++) accS[ni][e]=0.f;

    #pragma unroll
    for(int ks=0; ks<4; ks++){
      #pragma unroll
      for(int np=0; np<4; np++){
        unsigned kb[4];
        unsigned ad = sbK + (unsigned)(((np*16 + kj)*AT_STR + ks*16 + kd)*2);
        ldsm4(kb, ad);
        mma16816bf(accS[2*np],   qh[ks], kb);
        mma16816bf(accS[2*np+1], qh[ks], kb+2);
      }
    }

    #pragma unroll
    for(int ni=0; ni<8; ni++){
      float2 ktp = *(const float2*)&kts[ni*8 + 2*t];
      float z0 = attn_logit(accS[ni][0], qtL, cqL, rshL, BqL, ktp.x, lam, tau, spm);
      float z1 = attn_logit(accS[ni][1], qtL, cqL, rshL, BqL, ktp.y, lam, tau, spm);
      float z2 = attn_logit(accS[ni][2], qtH, cqH, rshH, BqH, ktp.x, lam, tau, spm);
      float z3 = attn_logit(accS[ni][3], qtH, cqH, rshH, BqH, ktp.y, lam, tau, spm);
      float p0 = __expf(z0), p1 = __expf(z1), p2 = __expf(z2), p3 = __expf(z3);
      lsumL += p0 + p1;
      lsumH += p2 + p3;
      accS[ni][0]=p0; accS[ni][1]=p1; accS[ni][2]=p2; accS[ni][3]=p3;
    }

    #pragma unroll
    for(int kc=0; kc<4; kc++){
      unsigned aP[4];
      packhi(accS[2*kc  ][0], accS[2*kc  ][1], aP[0]);
      packhi(accS[2*kc  ][2], accS[2*kc  ][3], aP[1]);
      packhi(accS[2*kc+1][0], accS[2*kc+1][1], aP[2]);
      packhi(accS[2*kc+1][2], accS[2*kc+1][3], aP[3]);
      #pragma unroll
      for(int nq=0; nq<4; nq++){
        unsigned voff = (unsigned)(((kc*16 + vj)*AT_STR + nq*16 + vc)*2);
        unsigned vb[4], vlb[4];
        ldsm4t(vb,  sbVh + voff);
        ldsm4t(vlb, sbVl + voff);
        mma16816bf(accO[2*nq],   aP, vb);
        mma16816bf(accO[2*nq+1], aP, vb+2);
        mma16816bf(accO[2*nq],   aP, vlb);
        mma16816bf(accO[2*nq+1], aP, vlb+2);
      }
    }
    __syncthreads();
  }

  float lL = lsumL, lH = lsumH;
  #pragma unroll
  for(int o=1;o<4;o<<=1){
    lL += __shfl_xor_sync(0xffffffffu, lL, o);
    lH += __shfl_xor_sync(0xffffffffu, lH, o);
  }
  float invL = 1.f/(lL*(1.f + 1e-8f));
  float invH = 1.f/(lH*(1.f + 1e-8f));

  float agL[8][2], agH[8][2];
  float nnL = 0.f, nnH = 0.f;
  #pragma unroll
  for(int ni=0;ni<8;ni++){
    agL[ni][0] = accO[ni][0]*invL; agL[ni][1] = accO[ni][1]*invL;
    agH[ni][0] = accO[ni][2]*invH; agH[ni][1] = accO[ni][3]*invH;
    nnL += agL[ni][0]*agL[ni][0] + agL[ni][1]*agL[ni][1];
    nnH += agH[ni][0]*agH[ni][0] + agH[ni][1]*agH[ni][1];
  }
  #pragma unroll
  for(int o=1;o<4;o<<=1){
    nnL += __shfl_xor_sync(0xffffffffu, nnL, o);
    nnH += __shfl_xor_sync(0xffffffffu, nnH, o);
  }
  nnL = sqrtf(nnL); nnH = sqrtf(nnH);
  float tL = coshf(nnL), tH = coshf(nnH);
  float sclL = sinhf(nnL)/fmaxf(nnL, 1e-8f);
  float sclH = sinhf(nnH)/fmaxf(nnH, 1e-8f);

  const int b_ = bh / HEADS, h = bh % HEADS;
  const int growL = b_*SEQ + rowL, growH = b_*SEQ + rowH;
  #pragma unroll
  for(int ni=0;ni<8;ni++){
    int c0 = ni*8 + 2*t;
    size_t iL = (size_t)growL*KP1 + 1 + h*HDIM + c0;
    size_t iH = (size_t)growH*KP1 + 1 + h*HDIM + c0;
    g_AINf[iL]     = __float2half(agL[ni][0]*sclL);
    g_AINf[iL + 1] = __float2half(agL[ni][1]*sclL);
    g_AINf[iH]     = __float2half(agH[ni][0]*sclH);
    g_AINf[iH + 1] = __float2half(agH[ni][1]*sclH);
  }
  if(t==0){
    g_Th[growL*HEADS + h] = tL;
    g_Th[growH*HEADS + h] = tH;
  }
}

// t_new
__global__ void tnew_kernel()
{
  int r = blockIdx.x*256 + threadIdx.x;
  if(r >= ROWS) return;
  float s = 0.f;
  #pragma unroll
  for(int h=0; h<HEADS; h++){ float t = g_Th[r*HEADS+h]; s += t*t; }
  g_AINf[(size_t)r*KP1] = __float2half(sqrtf(s - (float)(HEADS-1)));
}

// time col for mlp hidden
__global__ void time_mlp_kernel()
{
  __shared__ float red[8];
  int row = blockIdx.x, tid = threadIdx.x;
  float s = 0.f;
  #pragma unroll
  for(int q=0;q<12;q++){
    float x = __half2float(g_H1f[(size_t)row*KP2 + 1 + tid + q*256]);
    s += x*x;
  }
  s = blockSum(s, red);
  if(tid==0) g_H1f[(size_t)row*KP2] = __float2half(sqrtf(1.f + s));
}

// final
__global__ void final_kernel(float* __restrict__ out)
{
  __shared__ float red[8];
  int row = blockIdx.x, tid = threadIdx.x;
  float v[3]; float s = 0.f;
  #pragma unroll
  for(int q=0;q<3;q++){
    int j = tid + q*256;
    float x = g_G2[(size_t)row*D + j] + g_OUT[(size_t)row*D + j];
    v[q] = x; s += x*x;
  }
  s = blockSum(s, red);
  #pragma unroll
  for(int q=0;q<3;q++){
    int j = tid + q*256;
    out[(size_t)row*DH + 1 + j] = v[q];
  }
  if(tid==0) out[(size_t)row*DH] = sqrtf(1.f + s);
}

// ---------------------------------------------------------------------------
// Launch
// ---------------------------------------------------------------------------
extern "C" void kernel_launch(void* const* d_in, const int* in_sizes, int n_in,
                              void* d_out, int out_size)
{
  const float* x    = (const float*)d_in[0];
  const float* Wq   = (const float*)d_in[1];
  const float* Wk   = (const float*)d_in[2];
  const float* Wv   = (const float*)d_in[3];
  const float* Wo   = (const float*)d_in[4];
  const float* ln1g = (const float*)d_in[5];
  const float* ln1b = (const float*)d_in[6];
  const float* ln2g = (const float*)d_in[7];
  const float* ln2b = (const float*)d_in[8];
  const float* Wm1  = (const float*)d_in[9];
  const float* Wm2  = (const float*)d_in[10];
  const float* araw = (const float*)d_in[11];
  const float* traw = (const float*)d_in[12];
  const float* lraw = (const float*)d_in[13];
  float* out = (float*)d_out;

  float *pQKV, *pMO, *pOUT, *pG2;
  cudaGetSymbolAddress((void**)&pQKV, g_QKVf);
  cudaGetSymbolAddress((void**)&pMO,  g_MO);
  cudaGetSymbolAddress((void**)&pOUT, g_OUT);
  cudaGetSymbolAddress((void**)&pG2,  g_G2);

  __half *pX1f,*pAINf,*pHf,*pH1f;
  __half *pWqkvh,*pWqkvl,*pWoh,*pWol,*pW1h,*pW1l,*pW2h,*pW2l;
  cudaGetSymbolAddress((void**)&pX1f,  g_X1f);
  cudaGetSymbolAddress((void**)&pAINf, g_AINf);
  cudaGetSymbolAddress((void**)&pHf,   g_Hf);
  cudaGetSymbolAddress((void**)&pH1f,  g_H1f);
  cudaGetSymbolAddress((void**)&pWqkvh,g_Wqkvh);cudaGetSymbolAddress((void**)&pWqkvl,g_Wqkvl);
  cudaGetSymbolAddress((void**)&pWoh,  g_Woh);  cudaGetSymbolAddress((void**)&pWol,  g_Wol);
  cudaGetSymbolAddress((void**)&pW1h,  g_W1h);  cudaGetSymbolAddress((void**)&pW1l,  g_W1l);
  cudaGetSymbolAddress((void**)&pW2h,  g_W2h);  cudaGetSymbolAddress((void**)&pW2l,  g_W2l);

  cudaFuncSetAttribute(hgemm_kernel, cudaFuncAttributeMaxDynamicSharedMemorySize,
                       HG_SMEM_BYTES);
  cudaFuncSetAttribute(attn_kernel, cudaFuncAttributeMaxDynamicSharedMemorySize,
                       AT_SMEM_BYTES);

  // 0,1: weight converts for QKV/Wo
  {
    int tq = 3*D*DH;
    convsplit_qkv_kernel<<<(tq+255)/256,256>>>(Wq, Wk, Wv, pWqkvh, pWqkvl);
    int t1 = D*DH;
    convsplit_kernel<<<(t1+255)/256,256>>>(Wo, pWoh, pWol, DH, KP1, t1);
  }

  // 2: ln1 + add_time
  ln_addtime_kernel<<<ROWS,256>>>(x, DH, 1, nullptr, 0, 0, ln1g, ln1b, pX1f, nullptr);

  // 3: fused QKV projection
  dim3 gqkv(2304/128, ROWS/128);
  hgemm_kernel<<<gqkv,512,HG_SMEM_BYTES>>>(pX1f, pWqkvh,pWqkvl, pQKV,nullptr, KP1, 0, 1);

  // 4: prep
  prep_kernel<<<(BH*SEQ)/8, 256>>>();

  // 5: fused attention
  attn_kernel<<<dim3(SEQ/128, BH), 256, AT_SMEM_BYTES>>>(araw, traw, lraw);

  // 6: t_new
  tnew_kernel<<<ROWS/256, 256>>>();

  // 7: Wm1 convert (deferred)
  {
    int t2 = DM*DH;
    convsplit_kernel<<<(t2+255)/256,256>>>(Wm1, pW1h, pW1l, DH, KP1, t2);
  }

  // 8: Wo projection
  dim3 g768(D/128, ROWS/128);
  hgemm_kernel<<<g768,512,HG_SMEM_BYTES>>>(pAINf, pWoh,pWol, pMO,nullptr, KP1, D, 0);

  // 9: residual + ln2
  ln_addtime_kernel<<<ROWS,256>>>(pMO, D, 0, x, DH, 1, ln2g, ln2b, pHf, pOUT);

  // 10: MLP up with gelu
  dim3 g3072(DM/128, ROWS/128);
  hgemm_kernel<<<g3072,512,HG_SMEM_BYTES>>>(pHf, pW1h,pW1l, nullptr, pH1f+1, KP1, KP2, 2);

  // 11: Wm2 convert (deferred)
  {
    int t3 = D*DMH;
    convsplit_kernel<<<(t3+255)/256,256>>>(Wm2, pW2h, pW2l, DMH, KP2, t3);
  }

  // 12: mlp hidden time col
  time_mlp_kernel<<<ROWS,256>>>();

  // 13: MLP down
  hgemm_kernel<<<g768,512,HG_SMEM_BYTES>>>(pH1f, pW2h,pW2l, pG2,nullptr, KP2, D, 0);

  // 14: final
  final_kernel<<<ROWS,256>>>(out);
}

// round 13
// speedup vs baseline: 1.4118x; 1.0208x over previous
#include <cuda_runtime.h>
#include <cuda_bf16.h>
#include <cuda_fp16.h>
#include <math.h>
#include <cstdint>

// ---------------------------------------------------------------------------
// Problem constants
// ---------------------------------------------------------------------------
#define BATCH 4
#define SEQ   1024
#define D     768
#define DH    769
#define HEADS 12
#define HDIM  64
#define BH    (BATCH*HEADS)      // 48
#define ROWS  (BATCH*SEQ)        // 4096
#define DM    3072
#define DMH   3073
#define KP1   800
#define KP2   3104

// ---------------------------------------------------------------------------
// Scratch
// ---------------------------------------------------------------------------
__device__ float g_QKVf[3*BH*SEQ*HDIM];
__device__ float g_qt [BH*SEQ];
__device__ float g_kt [BH*SEQ];
__device__ float g_Th [ROWS*HEADS];
__device__ float g_MO [ROWS*D];
__device__ float g_OUT[ROWS*D];
__device__ float g_G2 [ROWS*D];

// fp16 per-head planes for attention (all single-plane now)
__device__ __half g_Qsp[BH*SEQ*HDIM];
__device__ __half g_Ksp[BH*SEQ*HDIM];
__device__ __half g_Vsp[BH*SEQ*HDIM];

// fp16 single-plane activations (GEMM A operands)
__device__ __half g_X1f [ROWS*KP1];
__device__ __half g_AINf[ROWS*KP1];
__device__ __half g_Hf  [ROWS*KP1];
__device__ __half g_H1f [ROWS*KP2];

// fp16 split weight planes (GEMM B operands)
__device__ __half g_Wqkvh[3*D*KP1], g_Wqkvl[3*D*KP1];
__device__ __half g_Woh[D*KP1],  g_Wol[D*KP1];
__device__ __half g_W1h[DM*KP1], g_W1l[DM*KP1];
__device__ __half g_W2h[D*KP2],  g_W2l[D*KP2];

// ---------------------------------------------------------------------------
// Helpers
// ---------------------------------------------------------------------------
__device__ __forceinline__ float warpSum(float v){
  #pragma unroll
  for(int o=16;o>0;o>>=1) v += __shfl_xor_sync(0xffffffffu, v, o);
  return v;
}
__device__ __forceinline__ float blockSum(float v, float* sh){
  int lane = threadIdx.x & 31, w = threadIdx.x >> 5;
  v = warpSum(v);
  if(lane==0) sh[w] = v;
  __syncthreads();
  float r = (threadIdx.x < 8) ? sh[threadIdx.x] : 0.f;
  if(w==0) r = warpSum(r);
  if(threadIdx.x==0) sh[0] = r;
  __syncthreads();
  r = sh[0];
  __syncthreads();
  return r;
}
__device__ __forceinline__ void splitStoreHf(__half* ph, __half* pl, float x){
  __half h = __float2half(x);
  *ph = h;
  *pl = __float2half(x - __half2float(h));
}
__device__ __forceinline__ void packhiHf(float a, float b, unsigned &h){
  __half2 hp; hp.x = __float2half(a); hp.y = __float2half(b);
  h = *(unsigned*)&hp;
}
__device__ __forceinline__ void cpasync16(void* s, const void* g){
  unsigned int sa = (unsigned int)__cvta_generic_to_shared(s);
  asm volatile("cp.async.cg.shared.global [%0], [%1], 16;\n" :: "r"(sa), "l"(g));
}
#define CP_COMMIT asm volatile("cp.async.commit_group;\n")
#define CP_WAIT(n) asm volatile("cp.async.wait_group %0;\n" :: "n"(n))

__device__ __forceinline__ void mma16816hf(float* d, const unsigned* a, const unsigned* b){
  asm volatile("mma.sync.aligned.m16n8k16.row.col.f32.f16.f16.f32 "
    "{%0,%1,%2,%3},{%4,%5,%6,%7},{%8,%9},{%0,%1,%2,%3};"
    : "+f"(d[0]),"+f"(d[1]),"+f"(d[2]),"+f"(d[3])
    : "r"(a[0]),"r"(a[1]),"r"(a[2]),"r"(a[3]),"r"(b[0]),"r"(b[1]));
}
__device__ __forceinline__ void ldsm4(unsigned* r, unsigned addr){
  asm volatile("ldmatrix.sync.aligned.m8n8.x4.shared.b16 {%0,%1,%2,%3}, [%4];"
    : "=r"(r[0]),"=r"(r[1]),"=r"(r[2]),"=r"(r[3]) : "r"(addr));
}
__device__ __forceinline__ void ldsm4t(unsigned* r, unsigned addr){
  asm volatile("ldmatrix.sync.aligned.m8n8.x4.trans.shared.b16 {%0,%1,%2,%3}, [%4];"
    : "=r"(r[0]),"=r"(r[1]),"=r"(r[2]),"=r"(r[3]) : "r"(addr));
}

// ---------------------------------------------------------------------------
// Weight split-converts (fp16 hi/lo)
// ---------------------------------------------------------------------------
__global__ void convsplit_kernel(const float* __restrict__ W,
                                 __half* __restrict__ Wh,
                                 __half* __restrict__ Wl,
                                 int Kk, int KPp, int total)
{
  int i = blockIdx.x*256 + threadIdx.x;
  if(i >= total) return;
  int r = i / Kk, c = i - r*Kk;
  splitStoreHf(Wh + (size_t)r*KPp + c, Wl + (size_t)r*KPp + c, W[i]);
}

__global__ void convsplit_qkv_kernel(const float* __restrict__ Wq,
                                     const float* __restrict__ Wk,
                                     const float* __restrict__ Wv,
                                     __half* __restrict__ Wh,
                                     __half* __restrict__ Wl)
{
  int i = blockIdx.x*256 + threadIdx.x;
  if(i >= 3*D*DH) return;
  int r = i / DH, c = i - r*DH;
  const float* src = (r < D) ? Wq : ((r < 2*D) ? Wk : Wv);
  int rl = (r < D) ? r : ((r < 2*D) ? r - D : r - 2*D);
  splitStoreHf(Wh + (size_t)r*KP1 + c, Wl + (size_t)r*KP1 + c, src[(size_t)rl*DH + c]);
}

// ---------------------------------------------------------------------------
// LayerNorm (+optional add) + add_time -> single fp16 plane
// ---------------------------------------------------------------------------
__global__ void ln_addtime_kernel(const float* __restrict__ in1, int ld1, int off1,
                                  const float* __restrict__ in2, int ld2, int off2,
                                  const float* __restrict__ gv, const float* __restrict__ bv,
                                  __half* __restrict__ outp,
                                  float* __restrict__ rawOut)
{
  __shared__ float red[8];
  int row = blockIdx.x, tid = threadIdx.x;
  float v[3];
  #pragma unroll
  for(int q=0;q<3;q++){
    int j = tid + q*256;
    float x = in1[(size_t)row*ld1 + off1 + j];
    if(in2) x += in2[(size_t)row*ld2 + off2 + j];
    v[q] = x;
    if(rawOut) rawOut[(size_t)row*D + j] = x;
  }
  float s  = v[0]+v[1]+v[2];
  float s2 = v[0]*v[0]+v[1]*v[1]+v[2]*v[2];
  s  = blockSum(s,  red);
  float mu = s * (1.f/768.f);
  s2 = blockSum(s2, red);
  float var = s2*(1.f/768.f) - mu*mu;
  float rstd = rsqrtf(var + 1e-5f);
  float w[3]; float n2 = 0.f;
  #pragma unroll
  for(int q=0;q<3;q++){
    int j = tid + q*256;
    w[q] = (v[q]-mu)*rstd*gv[j] + bv[j];
    n2 += w[q]*w[q];
  }
  n2 = blockSum(n2, red);
  #pragma unroll
  for(int q=0;q<3;q++){
    int j = tid + q*256;
    outp[(size_t)row*KP1 + 1 + j] = __float2half(w[q]);
  }
  if(tid==0) outp[(size_t)row*KP1] = __float2half(sqrtf(1.f + n2));
}

// ---------------------------------------------------------------------------
// fp16 2-term GEMM (verified R12): C[M,N] = A[M,K]*(Bh+Bl)[N,K]^T
// ---------------------------------------------------------------------------
#define HG_PLANE_H  5120
#define HG_STAGE_H  (3*HG_PLANE_H)
#define HG_STAGE_BYTES (HG_STAGE_H*2)
#define HG_SMEM_BYTES (3*HG_STAGE_BYTES)

__global__ void __launch_bounds__(512,1) hgemm_kernel(
    const __half* __restrict__ Ah,
    const __half* __restrict__ Bh, const __half* __restrict__ Bl,
    float* __restrict__ Cf, __half* __restrict__ Ch,
    int KP, int ldc, int mode)
{
  extern __shared__ __half smb[];
  int tid = threadIdx.x;
  int lane = tid & 31, wid = tid >> 5;
  int wm = wid >> 2, wn = wid & 3;
  int g = lane >> 2, t = lane & 3;
  int row0 = blockIdx.y*128, col0 = blockIdx.x*128;

  float acc[2][4][4];
  #pragma unroll
  for(int mi=0;mi<2;mi++)
    #pragma unroll
    for(int ni=0;ni<4;ni++)
      #pragma unroll
      for(int e=0;e<4;e++) acc[mi][ni][e]=0.f;

  const int niter = KP >> 5;
  const unsigned smemU = (unsigned)__cvta_generic_to_shared(smb);

  const int aRow = wm*32 + (lane&7) + ((lane>>3)&1)*8;
  const int aCol = ((lane>>4)&1)*8;
  const unsigned aOffH = (unsigned)((aRow*40 + aCol)*2);
  const int bRow8 = lane & 7;
  const int bSel  = (lane >> 3) & 1;
  const unsigned bOff4 = (unsigned)(10240 + ((bRow8)*40 + bSel*8)*2 + ((lane & 16) ? 10240 : 0));

  #define LOAD_STAGE(stg, k0) do{                                             \
    __half* s = smb + (stg)*HG_STAGE_H;                                       \
    _Pragma("unroll")                                                         \
    for(int q_=0;q_<3;q_++){                                                  \
      int idx_ = tid + q_*512;                                                \
      int p_ = idx_ >> 9, w_ = idx_ & 511;                                    \
      int r_ = w_ >> 2, cc_ = (w_ & 3)*8;                                     \
      const __half* src_ = (p_==0? Ah : (p_==1? Bh : Bl));                    \
      int grow_ = (p_==0? row0 : col0) + r_;                                  \
      cpasync16(s + p_*HG_PLANE_H + r_*40 + cc_,                              \
                src_ + (size_t)grow_*KP + (k0) + cc_);                        \
    }                                                                         \
    CP_COMMIT;                                                                \
  } while(0)

  LOAD_STAGE(0, 0);
  LOAD_STAGE(1, 32);

  for(int it=0; it<niter; it++){
    if(it == niter-1){ CP_WAIT(0); } else { CP_WAIT(1); }
    __syncthreads();
    if(it+2 < niter) LOAD_STAGE((it+2)%3, (it+2)<<5);

    const unsigned sb = smemU + (unsigned)((it%3)*HG_STAGE_BYTES);

    #pragma unroll
    for(int ks=0;ks<2;ks++){
      unsigned a_h[2][4];
      #pragma unroll
      for(int mi=0;mi<2;mi++){
        unsigned ad = sb + aOffH + (unsigned)(mi*1280 + ks*32);
        ldsm4(a_h[mi], ad);
      }
      unsigned bhl[4][4];
      #pragma unroll
      for(int ni=0;ni<4;ni++){
        unsigned bd = sb + bOff4 + (unsigned)(wn*2560 + ni*640 + ks*32);
        ldsm4(bhl[ni], bd);
      }
      #pragma unroll
      for(int mi=0;mi<2;mi++)
        #pragma unroll
        for(int ni=0;ni<4;ni++) mma16816hf(acc[mi][ni], a_h[mi], bhl[ni]);
      #pragma unroll
      for(int mi=0;mi<2;mi++)
        #pragma unroll
        for(int ni=0;ni<4;ni++) mma16816hf(acc[mi][ni], a_h[mi], bhl[ni]+2);
    }
  }

  int mat = blockIdx.x / 6;
  int cmatBase = mat*768;
  #pragma unroll
  for(int mi=0;mi<2;mi++){
    int rb = row0 + wm*32 + mi*16 + g;
    #pragma unroll
    for(int ni=0;ni<4;ni++){
      int cb = col0 + wn*32 + ni*8 + 2*t;
      float* a = acc[mi][ni];
      #pragma unroll
      for(int e=0;e<4;e++){
        int r = rb + (e>=2 ? 8 : 0);
        int c = cb + (e&1);
        float v = a[e];
        if(mode==2){
          v = 0.5f*v*(1.f + erff(v*0.70710678118654752f));
          Ch[(size_t)r*ldc + c] = __float2half(v);
        } else if(mode==1){
          int b_ = r >> 10, ii = r & 1023;
          int cmat = c - cmatBase;
          int h = cmat >> 6, cc2 = cmat & 63;
          Cf[(size_t)mat*(BH*SEQ*HDIM) + (size_t)(((b_*HEADS+h)<<10) + ii)*HDIM + cc2] = v;
        } else {
          Cf[(size_t)r*ldc + c] = v;
        }
      }
    }
  }
}

// ---------------------------------------------------------------------------
// Prep: qt, kt, v->v_tan; Q,K,V single fp16 planes.
// ---------------------------------------------------------------------------
__global__ void prep_kernel()
{
  int w = blockIdx.x*8 + (threadIdx.x>>5);
  int lane = threadIdx.x & 31;

  const float* q = g_QKVf + (size_t)w*HDIM;
  float qv[2]; float s = 0.f;
  #pragma unroll
  for(int e=0;e<2;e++){ qv[e] = q[lane+32*e]; s += qv[e]*qv[e]; }
  s = warpSum(s);
  if(lane==0) g_qt[w] = sqrtf(1.f + s);
  #pragma unroll
  for(int e=0;e<2;e++)
    g_Qsp[(size_t)w*HDIM + lane+32*e] = __float2half(qv[e]);

  const float* k = g_QKVf + (size_t)(BH*SEQ)*HDIM + (size_t)w*HDIM;
  float kv[2]; s = 0.f;
  #pragma unroll
  for(int e=0;e<2;e++){ kv[e] = k[lane+32*e]; s += kv[e]*kv[e]; }
  s = warpSum(s);
  if(lane==0) g_kt[w] = sqrtf(1.f + s);
  #pragma unroll
  for(int e=0;e<2;e++)
    g_Ksp[(size_t)w*HDIM + lane+32*e] = __float2half(kv[e]);

  const float* v = g_QKVf + (size_t)(2*BH*SEQ)*HDIM + (size_t)w*HDIM;
  float vv[2]; s = 0.f;
  #pragma unroll
  for(int e=0;e<2;e++){ vv[e] = v[lane+32*e]; s += vv[e]*vv[e]; }
  s = warpSum(s);
  float sn = sqrtf(s);
  float vt = sqrtf(1.f + s);
  float vc = fmaxf(vt, 1.0000001f);
  float dist = __logf(vc + sqrtf((vc-1.f)*(vc+1.f)));
  float scl = dist / fmaxf(sn, 1e-8f);
  #pragma unroll
  for(int e=0;e<2;e++)
    g_Vsp[(size_t)w*HDIM + lane+32*e] = __float2half(vv[e]*scl);
}

// ---------------------------------------------------------------------------
// fp16 tensor-core fused hyperbolic flash attention.
//   QK^T 1-term fp16; P.V 1-term fp16. 2 smem planes (K | V) double-buffered.
// ---------------------------------------------------------------------------
#define AT_STR   72
#define AT_PLANE (64*AT_STR)
#define AT_STAGE (2*AT_PLANE)
#define AT_SMEM_BYTES (2*AT_STAGE*2 + 2*64*4)

__device__ __forceinline__ float attn_logit(float sv, float qt, float cq, float rsh,
                                            float Bq, float ktj, float lam, float tau,
                                            float spm){
  float rawc = fmaxf(qt*ktj - sv, 1.0f);
  bool selfp = rawc < 1.00001f;
  float c = selfp ? 2.f : rawc;
  float x = (c-1.f)*(c+1.f);
  float rs = rsqrtf(fmaxf(x, 1e-12f));
  float sh = x*rs;
  float dist = __logf(c + sh);
  float ck = fmaxf(ktj, 1.0000001f);
  float Z = (rawc*cq - ck)*rs*rsh;
  Z = selfp ? 1.f : fminf(fmaxf(Z, -1.f), 1.f);
  float pen = -lam*__logf(1.f + dist*dist);
  float ent = __logf(1.f + __expf(Bq + Z - 0.1f)) - spm;
  return pen - tau*ent;
}

__global__ void __launch_bounds__(256,1) attn_kernel(
    const float* __restrict__ alpha_raw,
    const float* __restrict__ tau_raw,
    const float* __restrict__ lambda_raw)
{
  extern __shared__ __half smA[];
  float* ktsBuf = (float*)(smA + 2*AT_STAGE);

  const int bh = blockIdx.y;
  const int qrow0 = blockIdx.x*128;
  const int tid = threadIdx.x;
  const int lane = tid & 31, wid = tid >> 5;
  const int g = lane >> 2, t = lane & 3;
  const unsigned smemU = (unsigned)__cvta_generic_to_shared(smA);

  const float alpha = log1pf(expf(alpha_raw[0]));
  const float tau   = log1pf(expf(tau_raw[0]));
  const float lam   = log1pf(expf(lambda_raw[0]));
  const float spm   = log1pf(expf(-0.1f));

  // stage Q into stage-0 area, extract fragments
  {
    const __half* gQ = g_Qsp + ((size_t)bh*SEQ + qrow0)*HDIM;
    #pragma unroll
    for(int itn=0; itn<4; itn++){
      int ch = tid + itn*256;
      int r = ch >> 3, c0 = (ch & 7)*8;
      *(uint4*)(smA + r*AT_STR + c0) = *(const uint4*)(gQ + r*HDIM + c0);
    }
  }
  __syncthreads();

  unsigned qh[4][4];
  {
    const unsigned* pQ = (const unsigned*)smA;
    int rbase = wid*16 + g;
    #pragma unroll
    for(int ks=0; ks<4; ks++){
      int base = rbase*(AT_STR/2) + ks*8 + t;
      qh[ks][0]=pQ[base];               qh[ks][1]=pQ[base+8*(AT_STR/2)];
      qh[ks][2]=pQ[base+4];             qh[ks][3]=pQ[base+8*(AT_STR/2)+4];
    }
  }
  __syncthreads();

  const int rowL = qrow0 + wid*16 + g;
  const int rowH = rowL + 8;
  float qtL = g_qt[bh*SEQ + rowL], qtH = g_qt[bh*SEQ + rowH];
  float cqL = fmaxf(qtL, 1.0000001f), cqH = fmaxf(qtH, 1.0000001f);
  float ctL = fminf(__logf(cqL + sqrtf((cqL-1.f)*(cqL+1.f))), 40.f);
  float ctH = fminf(__logf(cqH + sqrtf((cqH-1.f)*(cqH+1.f))), 40.f);
  float rshL = 1.f/sinhf(ctL), rshH = 1.f/sinhf(ctH);
  float BqL = alpha*ctL/(1.f + alpha*ctL);
  float BqH = alpha*ctH/(1.f + alpha*ctH);

  float accO[8][4];
  #pragma unroll
  for(int ni=0;ni<8;ni++)
    #pragma unroll
    for(int e=0;e<4;e++) accO[ni][e]=0.f;
  float lsumL = 0.f, lsumH = 0.f;

  const __half* gK = g_Ksp + (size_t)bh*SEQ*HDIM;
  const __half* gV = g_Vsp + (size_t)bh*SEQ*HDIM;
  const float* gkt = g_kt + bh*SEQ;

  const int kj = (lane&7) + ((lane>>4)&1)*8;
  const int kd = ((lane>>3)&1)*8;
  const int vj = (lane&7) + ((lane>>3)&1)*8;
  const int vc = ((lane>>4)&1)*8;

  #define AT_LOAD(stg, jb) do{                                                  \
    __half* s = smA + (stg)*AT_STAGE;                                           \
    _Pragma("unroll")                                                           \
    for(int q_=0;q_<4;q_++){                                                    \
      int ch = tid + q_*256;                                                    \
      int pl = ch >> 9, cw = ch & 511;                                          \
      int r_ = cw >> 3, c_ = (cw & 7)*8;                                        \
      const __half* src = (pl==0? gK : gV);                                     \
      cpasync16(s + pl*AT_PLANE + r_*AT_STR + c_,                               \
                src + (size_t)((jb)+r_)*HDIM + c_);                             \
    }                                                                           \
    if(tid < 16) cpasync16(ktsBuf + (stg)*64 + tid*4, gkt + (jb) + tid*4);      \
    CP_COMMIT;                                                                  \
  } while(0)

  AT_LOAD(0, 0);

  for(int jt=0; jt<16; jt++){
    if(jt+1 < 16){ AT_LOAD((jt+1)&1, (jt+1)*64); CP_WAIT(1); }
    else         { CP_WAIT(0); }
    __syncthreads();

    const unsigned sbK = smemU + (unsigned)(((jt&1)*AT_STAGE)*2);
    const unsigned sbV = sbK + (unsigned)(AT_PLANE*2);
    const float* kts = ktsBuf + (jt&1)*64;

    // ---- S = Q.K^T (1-term fp16) ----
    float accS[8][4];
    #pragma unroll
    for(int ni=0;ni<8;ni++)
      #pragma unroll
      for(int e=0;e<4;e++) accS[ni][e]=0.f;

    #pragma unroll
    for(int ks=0; ks<4; ks++){
      #pragma unroll
      for(int np=0; np<4; np++){
        unsigned kb[4];
        unsigned ad = sbK + (unsigned)(((np*16 + kj)*AT_STR + ks*16 + kd)*2);
        ldsm4(kb, ad);
        mma16816hf(accS[2*np],   qh[ks], kb);
        mma16816hf(accS[2*np+1], qh[ks], kb+2);
      }
    }

    // ---- logits + exp ----
    #pragma unroll
    for(int ni=0; ni<8; ni++){
      float2 ktp = *(const float2*)&kts[ni*8 + 2*t];
      float z0 = attn_logit(accS[ni][0], qtL, cqL, rshL, BqL, ktp.x, lam, tau, spm);
      float z1 = attn_logit(accS[ni][1], qtL, cqL, rshL, BqL, ktp.y, lam, tau, spm);
      float z2 = attn_logit(accS[ni][2], qtH, cqH, rshH, BqH, ktp.x, lam, tau, spm);
      float z3 = attn_logit(accS[ni][3], qtH, cqH, rshH, BqH, ktp.y, lam, tau, spm);
      float p0 = __expf(z0), p1 = __expf(z1), p2 = __expf(z2), p3 = __expf(z3);
      lsumL += p0 + p1;
      lsumH += p2 + p3;
      accS[ni][0]=p0; accS[ni][1]=p1; accS[ni][2]=p2; accS[ni][3]=p3;
    }

    // ---- O += P.V (1-term fp16) ----
    #pragma unroll
    for(int kc=0; kc<4; kc++){
      unsigned aP[4];
      packhiHf(accS[2*kc  ][0], accS[2*kc  ][1], aP[0]);
      packhiHf(accS[2*kc  ][2], accS[2*kc  ][3], aP[1]);
      packhiHf(accS[2*kc+1][0], accS[2*kc+1][1], aP[2]);
      packhiHf(accS[2*kc+1][2], accS[2*kc+1][3], aP[3]);
      #pragma unroll
      for(int nq=0; nq<4; nq++){
        unsigned voff = (unsigned)(((kc*16 + vj)*AT_STR + nq*16 + vc)*2);
        unsigned vb[4];
        ldsm4t(vb, sbV + voff);
        mma16816hf(accO[2*nq],   aP, vb);
        mma16816hf(accO[2*nq+1], aP, vb+2);
      }
    }
    __syncthreads();
  }

  // ---- epilogue ----
  float lL = lsumL, lH = lsumH;
  #pragma unroll
  for(int o=1;o<4;o<<=1){
    lL += __shfl_xor_sync(0xffffffffu, lL, o);
    lH += __shfl_xor_sync(0xffffffffu, lH, o);
  }
  float invL = 1.f/(lL*(1.f + 1e-8f));
  float invH = 1.f/(lH*(1.f + 1e-8f));

  float agL[8][2], agH[8][2];
  float nnL = 0.f, nnH = 0.f;
  #pragma unroll
  for(int ni=0;ni<8;ni++){
    agL[ni][0] = accO[ni][0]*invL; agL[ni][1] = accO[ni][1]*invL;
    agH[ni][0] = accO[ni][2]*invH; agH[ni][1] = accO[ni][3]*invH;
    nnL += agL[ni][0]*agL[ni][0] + agL[ni][1]*agL[ni][1];
    nnH += agH[ni][0]*agH[ni][0] + agH[ni][1]*agH[ni][1];
  }
  #pragma unroll
  for(int o=1;o<4;o<<=1){
    nnL += __shfl_xor_sync(0xffffffffu, nnL, o);
    nnH += __shfl_xor_sync(0xffffffffu, nnH, o);
  }
  nnL = sqrtf(nnL); nnH = sqrtf(nnH);
  float tL = coshf(nnL), tH = coshf(nnH);
  float sclL = sinhf(nnL)/fmaxf(nnL, 1e-8f);
  float sclH = sinhf(nnH)/fmaxf(nnH, 1e-8f);

  const int b_ = bh / HEADS, h = bh % HEADS;
  const int growL = b_*SEQ + rowL, growH = b_*SEQ + rowH;
  #pragma unroll
  for(int ni=0;ni<8;ni++){
    int c0 = ni*8 + 2*t;
    size_t iL = (size_t)growL*KP1 + 1 + h*HDIM + c0;
    size_t iH = (size_t)growH*KP1 + 1 + h*HDIM + c0;
    g_AINf[iL]     = __float2half(agL[ni][0]*sclL);
    g_AINf[iL + 1] = __float2half(agL[ni][1]*sclL);
    g_AINf[iH]     = __float2half(agH[ni][0]*sclH);
    g_AINf[iH + 1] = __float2half(agH[ni][1]*sclH);
  }
  if(t==0){
    g_Th[growL*HEADS + h] = tL;
    g_Th[growH*HEADS + h] = tH;
  }
}

// t_new
__global__ void tnew_kernel()
{
  int r = blockIdx.x*256 + threadIdx.x;
  if(r >= ROWS) return;
  float s = 0.f;
  #pragma unroll
  for(int h=0; h<HEADS; h++){ float t = g_Th[r*HEADS+h]; s += t*t; }
  g_AINf[(size_t)r*KP1] = __float2half(sqrtf(s - (float)(HEADS-1)));
}

// time col for mlp hidden
__global__ void time_mlp_kernel()
{
  __shared__ float red[8];
  int row = blockIdx.x, tid = threadIdx.x;
  float s = 0.f;
  #pragma unroll
  for(int q=0;q<12;q++){
    float x = __half2float(g_H1f[(size_t)row*KP2 + 1 + tid + q*256]);
    s += x*x;
  }
  s = blockSum(s, red);
  if(tid==0) g_H1f[(size_t)row*KP2] = __float2half(sqrtf(1.f + s));
}

// final
__global__ void final_kernel(float* __restrict__ out)
{
  __shared__ float red[8];
  int row = blockIdx.x, tid = threadIdx.x;
  float v[3]; float s = 0.f;
  #pragma unroll
  for(int q=0;q<3;q++){
    int j = tid + q*256;
    float x = g_G2[(size_t)row*D + j] + g_OUT[(size_t)row*D + j];
    v[q] = x; s += x*x;
  }
  s = blockSum(s, red);
  #pragma unroll
  for(int q=0;q<3;q++){
    int j = tid + q*256;
    out[(size_t)row*DH + 1 + j] = v[q];
  }
  if(tid==0) out[(size_t)row*DH] = sqrtf(1.f + s);
}

// ---------------------------------------------------------------------------
// Launch
// ---------------------------------------------------------------------------
extern "C" void kernel_launch(void* const* d_in, const int* in_sizes, int n_in,
                              void* d_out, int out_size)
{
  const float* x    = (const float*)d_in[0];
  const float* Wq   = (const float*)d_in[1];
  const float* Wk   = (const float*)d_in[2];
  const float* Wv   = (const float*)d_in[3];
  const float* Wo   = (const float*)d_in[4];
  const float* ln1g = (const float*)d_in[5];
  const float* ln1b = (const float*)d_in[6];
  const float* ln2g = (const float*)d_in[7];
  const float* ln2b = (const float*)d_in[8];
  const float* Wm1  = (const float*)d_in[9];
  const float* Wm2  = (const float*)d_in[10];
  const float* araw = (const float*)d_in[11];
  const float* traw = (const float*)d_in[12];
  const float* lraw = (const float*)d_in[13];
  float* out = (float*)d_out;

  float *pQKV, *pMO, *pOUT, *pG2;
  cudaGetSymbolAddress((void**)&pQKV, g_QKVf);
  cudaGetSymbolAddress((void**)&pMO,  g_MO);
  cudaGetSymbolAddress((void**)&pOUT, g_OUT);
  cudaGetSymbolAddress((void**)&pG2,  g_G2);

  __half *pX1f,*pAINf,*pHf,*pH1f;
  __half *pWqkvh,*pWqkvl,*pWoh,*pWol,*pW1h,*pW1l,*pW2h,*pW2l;
  cudaGetSymbolAddress((void**)&pX1f,  g_X1f);
  cudaGetSymbolAddress((void**)&pAINf, g_AINf);
  cudaGetSymbolAddress((void**)&pHf,   g_Hf);
  cudaGetSymbolAddress((void**)&pH1f,  g_H1f);
  cudaGetSymbolAddress((void**)&pWqkvh,g_Wqkvh);cudaGetSymbolAddress((void**)&pWqkvl,g_Wqkvl);
  cudaGetSymbolAddress((void**)&pWoh,  g_Woh);  cudaGetSymbolAddress((void**)&pWol,  g_Wol);
  cudaGetSymbolAddress((void**)&pW1h,  g_W1h);  cudaGetSymbolAddress((void**)&pW1l,  g_W1l);
  cudaGetSymbolAddress((void**)&pW2h,  g_W2h);  cudaGetSymbolAddress((void**)&pW2l,  g_W2l);

  cudaFuncSetAttribute(hgemm_kernel, cudaFuncAttributeMaxDynamicSharedMemorySize,
                       HG_SMEM_BYTES);
  cudaFuncSetAttribute(attn_kernel, cudaFuncAttributeMaxDynamicSharedMemorySize,
                       AT_SMEM_BYTES);

  // 0,1: weight converts for QKV/Wo
  {
    int tq = 3*D*DH;
    convsplit_qkv_kernel<<<(tq+255)/256,256>>>(Wq, Wk, Wv, pWqkvh, pWqkvl);
    int t1 = D*DH;
    convsplit_kernel<<<(t1+255)/256,256>>>(Wo, pWoh, pWol, DH, KP1, t1);
  }

  // 2: ln1 + add_time
  ln_addtime_kernel<<<ROWS,256>>>(x, DH, 1, nullptr, 0, 0, ln1g, ln1b, pX1f, nullptr);

  // 3: fused QKV projection
  dim3 gqkv(2304/128, ROWS/128);
  hgemm_kernel<<<gqkv,512,HG_SMEM_BYTES>>>(pX1f, pWqkvh,pWqkvl, pQKV,nullptr, KP1, 0, 1);

  // 4: prep
  prep_kernel<<<(BH*SEQ)/8, 256>>>();

  // 5: fused attention
  attn_kernel<<<dim3(SEQ/128, BH), 256, AT_SMEM_BYTES>>>(araw, traw, lraw);

  // 6: t_new
  tnew_kernel<<<ROWS/256, 256>>>();

  // 7: Wm1 convert (deferred)
  {
    int t2 = DM*DH;
    convsplit_kernel<<<(t2+255)/256,256>>>(Wm1, pW1h, pW1l, DH, KP1, t2);
  }

  // 8: Wo projection
  dim3 g768(D/128, ROWS/128);
  hgemm_kernel<<<g768,512,HG_SMEM_BYTES>>>(pAINf, pWoh,pWol, pMO,nullptr, KP1, D, 0);

  // 9: residual + ln2
  ln_addtime_kernel<<<ROWS,256>>>(pMO, D, 0, x, DH, 1, ln2g, ln2b, pHf, pOUT);

  // 10: MLP up with gelu
  dim3 g3072(DM/128, ROWS/128);
  hgemm_kernel<<<g3072,512,HG_SMEM_BYTES>>>(pHf, pW1h,pW1l, nullptr, pH1f+1, KP1, KP2, 2);

  // 11: Wm2 convert (deferred)
  {
    int t3 = D*DMH;
    convsplit_kernel<<<(t3+255)/256,256>>>(Wm2, pW2h, pW2l, DMH, KP2, t3);
  }

  // 12: mlp hidden time col
  time_mlp_kernel<<<ROWS,256>>>();

  // 13: MLP down
  hgemm_kernel<<<g768,512,HG_SMEM_BYTES>>>(pH1f, pW2h,pW2l, pG2,nullptr, KP2, D, 0);

  // 14: final
  final_kernel<<<ROWS,256>>>(out);
}

// round 15
// speedup vs baseline: 1.8950x; 1.3423x over previous
#include <cuda_runtime.h>
#include <cuda_fp16.h>
#include <math.h>
#include <cstdint>

// ---------------------------------------------------------------------------
// Problem constants
// ---------------------------------------------------------------------------
#define BATCH 4
#define SEQ   1024
#define D     768
#define DH    769
#define HEADS 12
#define HDIM  64
#define BH    (BATCH*HEADS)      // 48
#define ROWS  (BATCH*SEQ)        // 4096
#define DM    3072
#define DMH   3073
#define KP1   800
#define KP2   3104

// ---------------------------------------------------------------------------
// Scratch
// ---------------------------------------------------------------------------
__device__ float g_QKVf[3*BH*SEQ*HDIM];
__device__ float g_qt [BH*SEQ];
__device__ float g_kt [BH*SEQ];
__device__ float g_Th [ROWS*HEADS];
__device__ float g_MO [ROWS*D];
__device__ float g_OUT[ROWS*D];
__device__ float g_G2 [ROWS*D];

// fp16 per-head planes for attention
__device__ __half g_Qsp[BH*SEQ*HDIM];
__device__ __half g_Ksp[BH*SEQ*HDIM];
__device__ __half g_Vsp[BH*SEQ*HDIM];

// fp16 single-plane activations (GEMM A operands)
__device__ __half g_X1f [ROWS*KP1];
__device__ __half g_AINf[ROWS*KP1];
__device__ __half g_Hf  [ROWS*KP1];
__device__ __half g_H1f [ROWS*KP2];

// fp16 single-plane weights (GEMM B operands)
__device__ __half g_Wqkv[3*D*KP1];
__device__ __half g_Wo [D*KP1];
__device__ __half g_W1 [DM*KP1];
__device__ __half g_W2 [D*KP2];

// ---------------------------------------------------------------------------
// Helpers
// ---------------------------------------------------------------------------
__device__ __forceinline__ float warpSum(float v){
  #pragma unroll
  for(int o=16;o>0;o>>=1) v += __shfl_xor_sync(0xffffffffu, v, o);
  return v;
}
__device__ __forceinline__ float blockSum(float v, float* sh){
  int lane = threadIdx.x & 31, w = threadIdx.x >> 5;
  v = warpSum(v);
  if(lane==0) sh[w] = v;
  __syncthreads();
  float r = (threadIdx.x < 8) ? sh[threadIdx.x] : 0.f;
  if(w==0) r = warpSum(r);
  if(threadIdx.x==0) sh[0] = r;
  __syncthreads();
  r = sh[0];
  __syncthreads();
  return r;
}
__device__ __forceinline__ void packhiHf(float a, float b, unsigned &h){
  __half2 hp; hp.x = __float2half(a); hp.y = __float2half(b);
  h = *(unsigned*)&hp;
}
__device__ __forceinline__ void cpasync16(void* s, const void* g){
  unsigned int sa = (unsigned int)__cvta_generic_to_shared(s);
  asm volatile("cp.async.cg.shared.global [%0], [%1], 16;\n" :: "r"(sa), "l"(g));
}
#define CP_COMMIT asm volatile("cp.async.commit_group;\n")
#define CP_WAIT(n) asm volatile("cp.async.wait_group %0;\n" :: "n"(n))

__device__ __forceinline__ void mma16816hf(float* d, const unsigned* a, const unsigned* b){
  asm volatile("mma.sync.aligned.m16n8k16.row.col.f32.f16.f16.f32 "
    "{%0,%1,%2,%3},{%4,%5,%6,%7},{%8,%9},{%0,%1,%2,%3};"
    : "+f"(d[0]),"+f"(d[1]),"+f"(d[2]),"+f"(d[3])
    : "r"(a[0]),"r"(a[1]),"r"(a[2]),"r"(a[3]),"r"(b[0]),"r"(b[1]));
}
__device__ __forceinline__ void ldsm4(unsigned* r, unsigned addr){
  asm volatile("ldmatrix.sync.aligned.m8n8.x4.shared.b16 {%0,%1,%2,%3}, [%4];"
    : "=r"(r[0]),"=r"(r[1]),"=r"(r[2]),"=r"(r[3]) : "r"(addr));
}
__device__ __forceinline__ void ldsm4t(unsigned* r, unsigned addr){
  asm volatile("ldmatrix.sync.aligned.m8n8.x4.trans.shared.b16 {%0,%1,%2,%3}, [%4];"
    : "=r"(r[0]),"=r"(r[1]),"=r"(r[2]),"=r"(r[3]) : "r"(addr));
}

// ---------------------------------------------------------------------------
// Weight converts (single fp16 plane)
// ---------------------------------------------------------------------------
__global__ void conv_kernel(const float* __restrict__ W,
                            __half* __restrict__ Wh,
                            int Kk, int KPp, int total)
{
  int i = blockIdx.x*256 + threadIdx.x;
  if(i >= total) return;
  int r = i / Kk, c = i - r*Kk;
  Wh[(size_t)r*KPp + c] = __float2half(W[i]);
}

__global__ void conv_qkv_kernel(const float* __restrict__ Wq,
                                const float* __restrict__ Wk,
                                const float* __restrict__ Wv,
                                __half* __restrict__ Wh)
{
  int i = blockIdx.x*256 + threadIdx.x;
  if(i >= 3*D*DH) return;
  int r = i / DH, c = i - r*DH;
  const float* src = (r < D) ? Wq : ((r < 2*D) ? Wk : Wv);
  int rl = (r < D) ? r : ((r < 2*D) ? r - D : r - 2*D);
  Wh[(size_t)r*KP1 + c] = __float2half(src[(size_t)rl*DH + c]);
}

// ---------------------------------------------------------------------------
// LayerNorm (+optional add) + add_time -> single fp16 plane
// ---------------------------------------------------------------------------
__global__ void ln_addtime_kernel(const float* __restrict__ in1, int ld1, int off1,
                                  const float* __restrict__ in2, int ld2, int off2,
                                  const float* __restrict__ gv, const float* __restrict__ bv,
                                  __half* __restrict__ outp,
                                  float* __restrict__ rawOut)
{
  __shared__ float red[8];
  int row = blockIdx.x, tid = threadIdx.x;
  float v[3];
  #pragma unroll
  for(int q=0;q<3;q++){
    int j = tid + q*256;
    float x = in1[(size_t)row*ld1 + off1 + j];
    if(in2) x += in2[(size_t)row*ld2 + off2 + j];
    v[q] = x;
    if(rawOut) rawOut[(size_t)row*D + j] = x;
  }
  float s  = v[0]+v[1]+v[2];
  float s2 = v[0]*v[0]+v[1]*v[1]+v[2]*v[2];
  s  = blockSum(s,  red);
  float mu = s * (1.f/768.f);
  s2 = blockSum(s2, red);
  float var = s2*(1.f/768.f) - mu*mu;
  float rstd = rsqrtf(var + 1e-5f);
  float w[3]; float n2 = 0.f;
  #pragma unroll
  for(int q=0;q<3;q++){
    int j = tid + q*256;
    w[q] = (v[q]-mu)*rstd*gv[j] + bv[j];
    n2 += w[q]*w[q];
  }
  n2 = blockSum(n2, red);
  #pragma unroll
  for(int q=0;q<3;q++){
    int j = tid + q*256;
    outp[(size_t)row*KP1 + 1 + j] = __float2half(w[q]);
  }
  if(tid==0) outp[(size_t)row*KP1] = __float2half(sqrtf(1.f + n2));
}

// ---------------------------------------------------------------------------
// Pure fp16 GEMM: C[M,N] = A[M,K]*B[N,K]^T  (1 MMA term)
//   128x128 CTA tile, BK=32, 16 warps (4x4), 32x32 warp tile, 512 threads,
//   3-stage cp.async pipeline, ldmatrix frags. 2 smem planes: A | B.
//   mode 0: fp32 out; 1: fused-QKV head-scatter; 2: gelu + fp16 out.
// ---------------------------------------------------------------------------
#define HG_PLANE_H  5120
#define HG_STAGE_H  (2*HG_PLANE_H)       // 10240 halves
#define HG_STAGE_BYTES (HG_STAGE_H*2)    // 20480
#define HG_SMEM_BYTES (3*HG_STAGE_BYTES) // 61440

__global__ void __launch_bounds__(512,1) hgemm_kernel(
    const __half* __restrict__ Ah,
    const __half* __restrict__ Bh,
    float* __restrict__ Cf, __half* __restrict__ Ch,
    int KP, int ldc, int mode)
{
  extern __shared__ __half smb[];
  int tid = threadIdx.x;
  int lane = tid & 31, wid = tid >> 5;
  int wm = wid >> 2, wn = wid & 3;
  int g = lane >> 2, t = lane & 3;
  int row0 = blockIdx.y*128, col0 = blockIdx.x*128;

  float acc[2][4][4];
  #pragma unroll
  for(int mi=0;mi<2;mi++)
    #pragma unroll
    for(int ni=0;ni<4;ni++)
      #pragma unroll
      for(int e=0;e<4;e++) acc[mi][ni][e]=0.f;

  const int niter = KP >> 5;
  const unsigned smemU = (unsigned)__cvta_generic_to_shared(smb);

  // A ldmatrix (per mi, per ks): 16 rows x 16 cols
  const int aRow = wm*32 + (lane&7) + ((lane>>3)&1)*8;
  const int aCol = ((lane>>4)&1)*8;
  const unsigned aOffH = (unsigned)((aRow*40 + aCol)*2);
  // B ldmatrix x4: octets = 4 consecutive k-octets of the same 8 rows
  const unsigned bOff = (unsigned)(10240 + (lane&7)*80 + (lane>>3)*16);

  #define LOAD_STAGE(stg, k0) do{                                             \
    __half* s = smb + (stg)*HG_STAGE_H;                                       \
    _Pragma("unroll")                                                         \
    for(int q_=0;q_<2;q_++){                                                  \
      int idx_ = tid + q_*512;                                                \
      int p_ = idx_ >> 9, w_ = idx_ & 511;                                    \
      int r_ = w_ >> 2, cc_ = (w_ & 3)*8;                                     \
      const __half* src_ = (p_==0? Ah : Bh);                                  \
      int grow_ = (p_==0? row0 : col0) + r_;                                  \
      cpasync16(s + p_*HG_PLANE_H + r_*40 + cc_,                              \
                src_ + (size_t)grow_*KP + (k0) + cc_);                        \
    }                                                                         \
    CP_COMMIT;                                                                \
  } while(0)

  LOAD_STAGE(0, 0);
  LOAD_STAGE(1, 32);

  for(int it=0; it<niter; it++){
    if(it == niter-1){ CP_WAIT(0); } else { CP_WAIT(1); }
    __syncthreads();
    if(it+2 < niter) LOAD_STAGE((it+2)%3, (it+2)<<5);

    const unsigned sb = smemU + (unsigned)((it%3)*HG_STAGE_BYTES);

    unsigned b[4][4];   // per ni: {k0-8, k8-16, k16-24, k24-32}
    #pragma unroll
    for(int ni=0;ni<4;ni++){
      unsigned bd = sb + bOff + (unsigned)(wn*2560 + ni*640);
      ldsm4(b[ni], bd);
    }
    #pragma unroll
    for(int ks=0;ks<2;ks++){
      unsigned a_h[2][4];
      #pragma unroll
      for(int mi=0;mi<2;mi++){
        unsigned ad = sb + aOffH + (unsigned)(mi*1280 + ks*32);
        ldsm4(a_h[mi], ad);
      }
      #pragma unroll
      for(int mi=0;mi<2;mi++)
        #pragma unroll
        for(int ni=0;ni<4;ni++) mma16816hf(acc[mi][ni], a_h[mi], b[ni]+2*ks);
    }
  }

  // ---- epilogue ----
  int mat = blockIdx.x / 6;
  int cmatBase = mat*768;
  #pragma unroll
  for(int mi=0;mi<2;mi++){
    int rb = row0 + wm*32 + mi*16 + g;
    #pragma unroll
    for(int ni=0;ni<4;ni++){
      int cb = col0 + wn*32 + ni*8 + 2*t;
      float* a = acc[mi][ni];
      #pragma unroll
      for(int e=0;e<4;e++){
        int r = rb + (e>=2 ? 8 : 0);
        int c = cb + (e&1);
        float v = a[e];
        if(mode==2){
          v = 0.5f*v*(1.f + erff(v*0.70710678118654752f));
          Ch[(size_t)r*ldc + c] = __float2half(v);
        } else if(mode==1){
          int b_ = r >> 10, ii = r & 1023;
          int cmat = c - cmatBase;
          int h = cmat >> 6, cc2 = cmat & 63;
          Cf[(size_t)mat*(BH*SEQ*HDIM) + (size_t)(((b_*HEADS+h)<<10) + ii)*HDIM + cc2] = v;
        } else {
          Cf[(size_t)r*ldc + c] = v;
        }
      }
    }
  }
}

// ---------------------------------------------------------------------------
// Prep: qt, kt, v->v_tan; Q,K,V single fp16 planes.
// ---------------------------------------------------------------------------
__global__ void prep_kernel()
{
  int w = blockIdx.x*8 + (threadIdx.x>>5);
  int lane = threadIdx.x & 31;

  const float* q = g_QKVf + (size_t)w*HDIM;
  float qv[2]; float s = 0.f;
  #pragma unroll
  for(int e=0;e<2;e++){ qv[e] = q[lane+32*e]; s += qv[e]*qv[e]; }
  s = warpSum(s);
  if(lane==0) g_qt[w] = sqrtf(1.f + s);
  #pragma unroll
  for(int e=0;e<2;e++)
    g_Qsp[(size_t)w*HDIM + lane+32*e] = __float2half(qv[e]);

  const float* k = g_QKVf + (size_t)(BH*SEQ)*HDIM + (size_t)w*HDIM;
  float kv[2]; s = 0.f;
  #pragma unroll
  for(int e=0;e<2;e++){ kv[e] = k[lane+32*e]; s += kv[e]*kv[e]; }
  s = warpSum(s);
  if(lane==0) g_kt[w] = sqrtf(1.f + s);
  #pragma unroll
  for(int e=0;e<2;e++)
    g_Ksp[(size_t)w*HDIM + lane+32*e] = __float2half(kv[e]);

  const float* v = g_QKVf + (size_t)(2*BH*SEQ)*HDIM + (size_t)w*HDIM;
  float vv[2]; s = 0.f;
  #pragma unroll
  for(int e=0;e<2;e++){ vv[e] = v[lane+32*e]; s += vv[e]*vv[e]; }
  s = warpSum(s);
  float sn = sqrtf(s);
  float vt = sqrtf(1.f + s);
  float vc = fmaxf(vt, 1.0000001f);
  float dist = __logf(vc + sqrtf((vc-1.f)*(vc+1.f)));
  float scl = dist / fmaxf(sn, 1e-8f);
  #pragma unroll
  for(int e=0;e<2;e++)
    g_Vsp[(size_t)w*HDIM + lane+32*e] = __float2half(vv[e]*scl);
}

// ---------------------------------------------------------------------------
// fp16 tensor-core fused hyperbolic flash attention (verified R13).
// ---------------------------------------------------------------------------
#define AT_STR   72
#define AT_PLANE (64*AT_STR)
#define AT_STAGE (2*AT_PLANE)
#define AT_SMEM_BYTES (2*AT_STAGE*2 + 2*64*4)

__device__ __forceinline__ float attn_logit(float sv, float qt, float cq, float rsh,
                                            float Bq, float ktj, float lam, float tau,
                                            float spm){
  float rawc = fmaxf(qt*ktj - sv, 1.0f);
  bool selfp = rawc < 1.00001f;
  float c = selfp ? 2.f : rawc;
  float x = (c-1.f)*(c+1.f);
  float rs = rsqrtf(fmaxf(x, 1e-12f));
  float sh = x*rs;
  float dist = __logf(c + sh);
  float ck = fmaxf(ktj, 1.0000001f);
  float Z = (rawc*cq - ck)*rs*rsh;
  Z = selfp ? 1.f : fminf(fmaxf(Z, -1.f), 1.f);
  float pen = -lam*__logf(1.f + dist*dist);
  float ent = __logf(1.f + __expf(Bq + Z - 0.1f)) - spm;
  return pen - tau*ent;
}

__global__ void __launch_bounds__(256,1) attn_kernel(
    const float* __restrict__ alpha_raw,
    const float* __restrict__ tau_raw,
    const float* __restrict__ lambda_raw)
{
  extern __shared__ __half smA[];
  float* ktsBuf = (float*)(smA + 2*AT_STAGE);

  const int bh = blockIdx.y;
  const int qrow0 = blockIdx.x*128;
  const int tid = threadIdx.x;
  const int lane = tid & 31, wid = tid >> 5;
  const int g = lane >> 2, t = lane & 3;
  const unsigned smemU = (unsigned)__cvta_generic_to_shared(smA);

  const float alpha = log1pf(expf(alpha_raw[0]));
  const float tau   = log1pf(expf(tau_raw[0]));
  const float lam   = log1pf(expf(lambda_raw[0]));
  const float spm   = log1pf(expf(-0.1f));

  {
    const __half* gQ = g_Qsp + ((size_t)bh*SEQ + qrow0)*HDIM;
    #pragma unroll
    for(int itn=0; itn<4; itn++){
      int ch = tid + itn*256;
      int r = ch >> 3, c0 = (ch & 7)*8;
      *(uint4*)(smA + r*AT_STR + c0) = *(const uint4*)(gQ + r*HDIM + c0);
    }
  }
  __syncthreads();

  unsigned qh[4][4];
  {
    const unsigned* pQ = (const unsigned*)smA;
    int rbase = wid*16 + g;
    #pragma unroll
    for(int ks=0; ks<4; ks++){
      int base = rbase*(AT_STR/2) + ks*8 + t;
      qh[ks][0]=pQ[base];               qh[ks][1]=pQ[base+8*(AT_STR/2)];
      qh[ks][2]=pQ[base+4];             qh[ks][3]=pQ[base+8*(AT_STR/2)+4];
    }
  }
  __syncthreads();

  const int rowL = qrow0 + wid*16 + g;
  const int rowH = rowL + 8;
  float qtL = g_qt[bh*SEQ + rowL], qtH = g_qt[bh*SEQ + rowH];
  float cqL = fmaxf(qtL, 1.0000001f), cqH = fmaxf(qtH, 1.0000001f);
  float ctL = fminf(__logf(cqL + sqrtf((cqL-1.f)*(cqL+1.f))), 40.f);
  float ctH = fminf(__logf(cqH + sqrtf((cqH-1.f)*(cqH+1.f))), 40.f);
  float rshL = 1.f/sinhf(ctL), rshH = 1.f/sinhf(ctH);
  float BqL = alpha*ctL/(1.f + alpha*ctL);
  float BqH = alpha*ctH/(1.f + alpha*ctH);

  float accO[8][4];
  #pragma unroll
  for(int ni=0;ni<8;ni++)
    #pragma unroll
    for(int e=0;e<4;e++) accO[ni][e]=0.f;
  float lsumL = 0.f, lsumH = 0.f;

  const __half* gK = g_Ksp + (size_t)bh*SEQ*HDIM;
  const __half* gV = g_Vsp + (size_t)bh*SEQ*HDIM;
  const float* gkt = g_kt + bh*SEQ;

  const int kj = (lane&7) + ((lane>>4)&1)*8;
  const int kd = ((lane>>3)&1)*8;
  const int vj = (lane&7) + ((lane>>3)&1)*8;
  const int vc = ((lane>>4)&1)*8;

  #define AT_LOAD(stg, jb) do{                                                  \
    __half* s = smA + (stg)*AT_STAGE;                                           \
    _Pragma("unroll")                                                           \
    for(int q_=0;q_<4;q_++){                                                    \
      int ch = tid + q_*256;                                                    \
      int pl = ch >> 9, cw = ch & 511;                                          \
      int r_ = cw >> 3, c_ = (cw & 7)*8;                                        \
      const __half* src = (pl==0? gK : gV);                                     \
      cpasync16(s + pl*AT_PLANE + r_*AT_STR + c_,                               \
                src + (size_t)((jb)+r_)*HDIM + c_);                             \
    }                                                                           \
    if(tid < 16) cpasync16(ktsBuf + (stg)*64 + tid*4, gkt + (jb) + tid*4);      \
    CP_COMMIT;                                                                  \
  } while(0)

  AT_LOAD(0, 0);

  for(int jt=0; jt<16; jt++){
    if(jt+1 < 16){ AT_LOAD((jt+1)&1, (jt+1)*64); CP_WAIT(1); }
    else         { CP_WAIT(0); }
    __syncthreads();

    const unsigned sbK = smemU + (unsigned)(((jt&1)*AT_STAGE)*2);
    const unsigned sbV = sbK + (unsigned)(AT_PLANE*2);
    const float* kts = ktsBuf + (jt&1)*64;

    float accS[8][4];
    #pragma unroll
    for(int ni=0;ni<8;ni++)
      #pragma unroll
      for(int e=0;e<4;e++) accS[ni][e]=0.f;

    #pragma unroll
    for(int ks=0; ks<4; ks++){
      #pragma unroll
      for(int np=0; np<4; np++){
        unsigned kb[4];
        unsigned ad = sbK + (unsigned)(((np*16 + kj)*AT_STR + ks*16 + kd)*2);
        ldsm4(kb, ad);
        mma16816hf(accS[2*np],   qh[ks], kb);
        mma16816hf(accS[2*np+1], qh[ks], kb+2);
      }
    }

    #pragma unroll
    for(int ni=0; ni<8; ni++){
      float2 ktp = *(const float2*)&kts[ni*8 + 2*t];
      float z0 = attn_logit(accS[ni][0], qtL, cqL, rshL, BqL, ktp.x, lam, tau, spm);
      float z1 = attn_logit(accS[ni][1], qtL, cqL, rshL, BqL, ktp.y, lam, tau, spm);
      float z2 = attn_logit(accS[ni][2], qtH, cqH, rshH, BqH, ktp.x, lam, tau, spm);
      float z3 = attn_logit(accS[ni][3], qtH, cqH, rshH, BqH, ktp.y, lam, tau, spm);
      float p0 = __expf(z0), p1 = __expf(z1), p2 = __expf(z2), p3 = __expf(z3);
      lsumL += p0 + p1;
      lsumH += p2 + p3;
      accS[ni][0]=p0; accS[ni][1]=p1; accS[ni][2]=p2; accS[ni][3]=p3;
    }

    #pragma unroll
    for(int kc=0; kc<4; kc++){
      unsigned aP[4];
      packhiHf(accS[2*kc  ][0], accS[2*kc  ][1], aP[0]);
      packhiHf(accS[2*kc  ][2], accS[2*kc  ][3], aP[1]);
      packhiHf(accS[2*kc+1][0], accS[2*kc+1][1], aP[2]);
      packhiHf(accS[2*kc+1][2], accS[2*kc+1][3], aP[3]);
      #pragma unroll
      for(int nq=0; nq<4; nq++){
        unsigned voff = (unsigned)(((kc*16 + vj)*AT_STR + nq*16 + vc)*2);
        unsigned vb[4];
        ldsm4t(vb, sbV + voff);
        mma16816hf(accO[2*nq],   aP, vb);
        mma16816hf(accO[2*nq+1], aP, vb+2);
      }
    }
    __syncthreads();
  }

  float lL = lsumL, lH = lsumH;
  #pragma unroll
  for(int o=1;o<4;o<<=1){
    lL += __shfl_xor_sync(0xffffffffu, lL, o);
    lH += __shfl_xor_sync(0xffffffffu, lH, o);
  }
  float invL = 1.f/(lL*(1.f + 1e-8f));
  float invH = 1.f/(lH*(1.f + 1e-8f));

  float agL[8][2], agH[8][2];
  float nnL = 0.f, nnH = 0.f;
  #pragma unroll
  for(int ni=0;ni<8;ni++){
    agL[ni][0] = accO[ni][0]*invL; agL[ni][1] = accO[ni][1]*invL;
    agH[ni][0] = accO[ni][2]*invH; agH[ni][1] = accO[ni][3]*invH;
    nnL += agL[ni][0]*agL[ni][0] + agL[ni][1]*agL[ni][1];
    nnH += agH[ni][0]*agH[ni][0] + agH[ni][1]*agH[ni][1];
  }
  #pragma unroll
  for(int o=1;o<4;o<<=1){
    nnL += __shfl_xor_sync(0xffffffffu, nnL, o);
    nnH += __shfl_xor_sync(0xffffffffu, nnH, o);
  }
  nnL = sqrtf(nnL); nnH = sqrtf(nnH);
  float tL = coshf(nnL), tH = coshf(nnH);
  float sclL = sinhf(nnL)/fmaxf(nnL, 1e-8f);
  float sclH = sinhf(nnH)/fmaxf(nnH, 1e-8f);

  const int b_ = bh / HEADS, h = bh % HEADS;
  const int growL = b_*SEQ + rowL, growH = b_*SEQ + rowH;
  #pragma unroll
  for(int ni=0;ni<8;ni++){
    int c0 = ni*8 + 2*t;
    size_t iL = (size_t)growL*KP1 + 1 + h*HDIM + c0;
    size_t iH = (size_t)growH*KP1 + 1 + h*HDIM + c0;
    g_AINf[iL]     = __float2half(agL[ni][0]*sclL);
    g_AINf[iL + 1] = __float2half(agL[ni][1]*sclL);
    g_AINf[iH]     = __float2half(agH[ni][0]*sclH);
    g_AINf[iH + 1] = __float2half(agH[ni][1]*sclH);
  }
  if(t==0){
    g_Th[growL*HEADS + h] = tL;
    g_Th[growH*HEADS + h] = tH;
  }
}

// t_new
__global__ void tnew_kernel()
{
  int r = blockIdx.x*256 + threadIdx.x;
  if(r >= ROWS) return;
  float s = 0.f;
  #pragma unroll
  for(int h=0; h<HEADS; h++){ float t = g_Th[r*HEADS+h]; s += t*t; }
  g_AINf[(size_t)r*KP1] = __float2half(sqrtf(s - (float)(HEADS-1)));
}

// time col for mlp hidden
__global__ void time_mlp_kernel()
{
  __shared__ float red[8];
  int row = blockIdx.x, tid = threadIdx.x;
  float s = 0.f;
  #pragma unroll
  for(int q=0;q<12;q++){
    float x = __half2float(g_H1f[(size_t)row*KP2 + 1 + tid + q*256]);
    s += x*x;
  }
  s = blockSum(s, red);
  if(tid==0) g_H1f[(size_t)row*KP2] = __float2half(sqrtf(1.f + s));
}

// final
__global__ void final_kernel(float* __restrict__ out)
{
  __shared__ float red[8];
  int row = blockIdx.x, tid = threadIdx.x;
  float v[3]; float s = 0.f;
  #pragma unroll
  for(int q=0;q<3;q++){
    int j = tid + q*256;
    float x = g_G2[(size_t)row*D + j] + g_OUT[(size_t)row*D + j];
    v[q] = x; s += x*x;
  }
  s = blockSum(s, red);
  #pragma unroll
  for(int q=0;q<3;q++){
    int j = tid + q*256;
    out[(size_t)row*DH + 1 + j] = v[q];
  }
  if(tid==0) out[(size_t)row*DH] = sqrtf(1.f + s);
}

// ---------------------------------------------------------------------------
// Launch
// ---------------------------------------------------------------------------
extern "C" void kernel_launch(void* const* d_in, const int* in_sizes, int n_in,
                              void* d_out, int out_size)
{
  const float* x    = (const float*)d_in[0];
  const float* Wq   = (const float*)d_in[1];
  const float* Wk   = (const float*)d_in[2];
  const float* Wv   = (const float*)d_in[3];
  const float* Wo   = (const float*)d_in[4];
  const float* ln1g = (const float*)d_in[5];
  const float* ln1b = (const float*)d_in[6];
  const float* ln2g = (const float*)d_in[7];
  const float* ln2b = (const float*)d_in[8];
  const float* Wm1  = (const float*)d_in[9];
  const float* Wm2  = (const float*)d_in[10];
  const float* araw = (const float*)d_in[11];
  const float* traw = (const float*)d_in[12];
  const float* lraw = (const float*)d_in[13];
  float* out = (float*)d_out;

  float *pQKV, *pMO, *pOUT, *pG2;
  cudaGetSymbolAddress((void**)&pQKV, g_QKVf);
  cudaGetSymbolAddress((void**)&pMO,  g_MO);
  cudaGetSymbolAddress((void**)&pOUT, g_OUT);
  cudaGetSymbolAddress((void**)&pG2,  g_G2);

  __half *pX1f,*pAINf,*pHf,*pH1f;
  __half *pWqkv,*pWo,*pW1,*pW2;
  cudaGetSymbolAddress((void**)&pX1f,  g_X1f);
  cudaGetSymbolAddress((void**)&pAINf, g_AINf);
  cudaGetSymbolAddress((void**)&pHf,   g_Hf);
  cudaGetSymbolAddress((void**)&pH1f,  g_H1f);
  cudaGetSymbolAddress((void**)&pWqkv, g_Wqkv);
  cudaGetSymbolAddress((void**)&pWo,   g_Wo);
  cudaGetSymbolAddress((void**)&pW1,   g_W1);
  cudaGetSymbolAddress((void**)&pW2,   g_W2);

  cudaFuncSetAttribute(hgemm_kernel, cudaFuncAttributeMaxDynamicSharedMemorySize,
                       HG_SMEM_BYTES);
  cudaFuncSetAttribute(attn_kernel, cudaFuncAttributeMaxDynamicSharedMemorySize,
                       AT_SMEM_BYTES);

  // 0,1: weight converts for QKV/Wo
  {
    int tq = 3*D*DH;
    conv_qkv_kernel<<<(tq+255)/256,256>>>(Wq, Wk, Wv, pWqkv);
    int t1 = D*DH;
    conv_kernel<<<(t1+255)/256,256>>>(Wo, pWo, DH, KP1, t1);
  }

  // 2: ln1 + add_time
  ln_addtime_kernel<<<ROWS,256>>>(x, DH, 1, nullptr, 0, 0, ln1g, ln1b, pX1f, nullptr);

  // 3: fused QKV projection
  dim3 gqkv(2304/128, ROWS/128);
  hgemm_kernel<<<gqkv,512,HG_SMEM_BYTES>>>(pX1f, pWqkv, pQKV,nullptr, KP1, 0, 1);

  // 4: prep
  prep_kernel<<<(BH*SEQ)/8, 256>>>();

  // 5: fused attention
  attn_kernel<<<dim3(SEQ/128, BH), 256, AT_SMEM_BYTES>>>(araw, traw, lraw);

  // 6: t_new
  tnew_kernel<<<ROWS/256, 256>>>();

  // 7: Wm1 convert (deferred)
  {
    int t2 = DM*DH;
    conv_kernel<<<(t2+255)/256,256>>>(Wm1, pW1, DH, KP1, t2);
  }

  // 8: Wo projection
  dim3 g768(D/128, ROWS/128);
  hgemm_kernel<<<g768,512,HG_SMEM_BYTES>>>(pAINf, pWo, pMO,nullptr, KP1, D, 0);

  // 9: residual + ln2
  ln_addtime_kernel<<<ROWS,256>>>(pMO, D, 0, x, DH, 1, ln2g, ln2b, pHf, pOUT);

  // 10: MLP up with gelu
  dim3 g3072(DM/128, ROWS/128);
  hgemm_kernel<<<g3072,512,HG_SMEM_BYTES>>>(pHf, pW1, nullptr, pH1f+1, KP1, KP2, 2);

  // 11: Wm2 convert (deferred)
  {
    int t3 = D*DMH;
    conv_kernel<<<(t3+255)/256,256>>>(Wm2, pW2, DMH, KP2, t3);
  }

  // 12: mlp hidden time col
  time_mlp_kernel<<<ROWS,256>>>();

  // 13: MLP down
  hgemm_kernel<<<g768,512,HG_SMEM_BYTES>>>(pH1f, pW2, pG2,nullptr, KP2, D, 0);

  // 14: final
  final_kernel<<<ROWS,256>>>(out);
}